// round 1
// baseline (speedup 1.0000x reference)
#include <cuda_runtime.h>
#include <math.h>
#include <stdint.h>

// ---------------- problem constants ----------------
#define DIM     768
#define BATCH   16
#define SEQ     197
#define MTOK    (BATCH*SEQ)     // 3152
#define NPATCH  196
#define TPAT    (BATCH*NPATCH)  // 3136
#define DSTATE  16
#define DTRANK  32
#define NCLS    1000
#define DEPTH   12

// ---------------- static device scratch (allocation-free) ----------------
__device__ float g_xp  [TPAT*DIM];
__device__ float g_xp2 [TPAT*DIM];
__device__ float g_h   [MTOK*DIM];
__device__ float g_xn  [MTOK*DIM];
__device__ float g_xz  [MTOK*DIM];
__device__ float g_uf  [MTOK*DIM];
__device__ float g_ub  [MTOK*DIM];
__device__ float g_dbcf[MTOK*64];
__device__ float g_dbcb[MTOK*64];
__device__ float g_df  [MTOK*DIM];
__device__ float g_db  [MTOK*DIM];
__device__ float g_y1  [MTOK*DIM];
__device__ float g_y2  [MTOK*DIM];
__device__ float g_pool [BATCH*DIM];
__device__ float g_pooln[BATCH*DIM];

// ---------------- helpers ----------------
__device__ __forceinline__ float softplus_f(float x) {
    if (x > 20.f) return x;
    return log1pf(__expf(x));
}

// ---------------- patchify: x(b,c,224,224) -> xp(3136, 768) ----------------
__global__ void patchify_kernel(const float* __restrict__ x, float* __restrict__ xp) {
    int idx = blockIdx.x * blockDim.x + threadIdx.x;   // < TPAT*DIM
    int t = idx / DIM;
    int f = idx % DIM;
    int b = t / NPATCH, hw = t % NPATCH;
    int hh = hw / 14, ww = hw % 14;
    int c = f % 3, pp = f / 3;
    int p1 = pp / 16, p2 = pp % 16;
    xp[idx] = x[(((size_t)(b*3 + c)*224) + hh*16 + p1)*224 + ww*16 + p2];
}

// ---------------- h init: h(16,197,768) = [cls ; xp2] ----------------
__global__ void h_init_kernel(const float* __restrict__ xp2,
                              const float* __restrict__ cls,
                              float* __restrict__ h) {
    int idx = blockIdx.x * blockDim.x + threadIdx.x;   // < MTOK*DIM
    int r = idx % (SEQ*DIM);
    int b = idx / (SEQ*DIM);
    int s = r / DIM, d = r % DIM;
    h[idx] = (s == 0) ? cls[d] : xp2[((size_t)(b*NPATCH + s - 1))*DIM + d];
}

// ---------------- layernorm over rows of width 768 ----------------
__global__ void ln_kernel(const float* __restrict__ in, float* __restrict__ out,
                          const float* __restrict__ g, const float* __restrict__ bv) {
    int row = blockIdx.x;
    const float* xr = in + (size_t)row * DIM;
    float* orow = out + (size_t)row * DIM;
    int tid = threadIdx.x;                  // 256 threads, 3 elems each
    float v0 = xr[tid], v1 = xr[tid + 256], v2 = xr[tid + 512];
    __shared__ float red[256];
    red[tid] = v0 + v1 + v2;
    __syncthreads();
    #pragma unroll
    for (int o = 128; o > 0; o >>= 1) { if (tid < o) red[tid] += red[tid + o]; __syncthreads(); }
    float mean = red[0] * (1.f / 768.f);
    __syncthreads();
    float d0 = v0 - mean, d1 = v1 - mean, d2 = v2 - mean;
    red[tid] = d0*d0 + d1*d1 + d2*d2;
    __syncthreads();
    #pragma unroll
    for (int o = 128; o > 0; o >>= 1) { if (tid < o) red[tid] += red[tid + o]; __syncthreads(); }
    float rstd = rsqrtf(red[0] * (1.f / 768.f) + 1e-5f);
    orow[tid]       = d0 * rstd * g[tid]       + bv[tid];
    orow[tid + 256] = d1 * rstd * g[tid + 256] + bv[tid + 256];
    orow[tid + 512] = d2 * rstd * g[tid + 512] + bv[tid + 512];
}

// ---------------- tiled SIMT GEMM ----------------
// C[M,N] = act( A[M,K](lda) * B + bias )
// TRANSB=false: B is (K,N) row-major.  TRANSB=true: B is (N,K) row-major (C=A*B^T).
// ACT: 0=none, 1=softplus
template<int BM,int BN,int BK,int TM,int TN,bool TRANSB,int ACT>
__global__ void __launch_bounds__((BM/TM)*(BN/TN))
gemm_kernel(const float* __restrict__ A, int lda,
            const float* __restrict__ B,
            const float* __restrict__ bias,
            float* __restrict__ C, int M, int N, int K)
{
    constexpr int TX = BN / TN;
    constexpr int TY = BM / TM;
    constexpr int THREADS = TX * TY;
    constexpr int KV = BK / 4;
    static_assert(BM * KV == THREADS, "A tile load mapping");
    static_assert(!TRANSB || BN * KV == THREADS, "B^T tile load mapping");
    static_assert(TRANSB || (BK * (BN/4)) == THREADS, "B tile load mapping");

    __shared__ __align__(16) float As[BK][BM];
    __shared__ __align__(16) float Bs[BK][BN];

    int tid = threadIdx.x;
    int n0 = blockIdx.x * BN;
    int m0 = blockIdx.y * BM;
    int tx = tid % TX, ty = tid / TX;

    float acc[TM][TN];
    #pragma unroll
    for (int i = 0; i < TM; i++)
        #pragma unroll
        for (int j = 0; j < TN; j++) acc[i][j] = 0.f;

    int arow = tid / KV;
    int acol = (tid % KV) * 4;
    int brow, bcol;
    if (!TRANSB) { brow = tid / (BN/4); bcol = (tid % (BN/4)) * 4; }
    else         { brow = tid / KV;     bcol = (tid % KV) * 4; }

    for (int k0 = 0; k0 < K; k0 += BK) {
        float4 av = make_float4(0.f, 0.f, 0.f, 0.f);
        if (m0 + arow < M)
            av = *(const float4*)(A + (size_t)(m0 + arow) * lda + k0 + acol);
        As[acol + 0][arow] = av.x; As[acol + 1][arow] = av.y;
        As[acol + 2][arow] = av.z; As[acol + 3][arow] = av.w;

        if (!TRANSB) {
            float4 bvv = *(const float4*)(B + (size_t)(k0 + brow) * N + n0 + bcol);
            *(float4*)&Bs[brow][bcol] = bvv;
        } else {
            float4 bvv = *(const float4*)(B + (size_t)(n0 + brow) * K + k0 + bcol);
            Bs[bcol + 0][brow] = bvv.x; Bs[bcol + 1][brow] = bvv.y;
            Bs[bcol + 2][brow] = bvv.z; Bs[bcol + 3][brow] = bvv.w;
        }
        __syncthreads();

        #pragma unroll
        for (int kk = 0; kk < BK; kk++) {
            float ar[TM], br[TN];
            #pragma unroll
            for (int i = 0; i < TM; i += 4) {
                float4 t = *(const float4*)&As[kk][ty * TM + i];
                ar[i] = t.x; ar[i+1] = t.y; ar[i+2] = t.z; ar[i+3] = t.w;
            }
            #pragma unroll
            for (int j = 0; j < TN; j += 4) {
                float4 t = *(const float4*)&Bs[kk][tx * TN + j];
                br[j] = t.x; br[j+1] = t.y; br[j+2] = t.z; br[j+3] = t.w;
            }
            #pragma unroll
            for (int i = 0; i < TM; i++)
                #pragma unroll
                for (int j = 0; j < TN; j++)
                    acc[i][j] = fmaf(ar[i], br[j], acc[i][j]);
        }
        __syncthreads();
    }

    #pragma unroll
    for (int i = 0; i < TM; i++) {
        int m = m0 + ty * TM + i;
        if (m < M) {
            #pragma unroll
            for (int j = 0; j < TN; j++) {
                int n = n0 + tx * TN + j;
                float v = acc[i][j] + (bias ? bias[n] : 0.f);
                if (ACT == 1) v = softplus_f(v);
                C[(size_t)m * N + n] = v;
            }
        }
    }
}

// ---------------- selective scan ----------------
// 16 threads per (b, ed): thread n holds state_n; serial over l=197.
// y[b,l,ed] = sum_n(state_n * C_n) + D[ed]*u
__global__ void __launch_bounds__(256)
scan_kernel(const float* __restrict__ u, const float* __restrict__ delta,
            const float* __restrict__ dbc, const float* __restrict__ A_log,
            const float* __restrict__ D, float* __restrict__ y)
{
    int g = blockIdx.x * 16 + (threadIdx.x >> 4);   // 0..12287  (b*768+ed)
    int n = threadIdx.x & 15;
    int b = g / DIM;
    int ed = g % DIM;

    float Aval = -__expf(A_log[ed * DSTATE + n]);
    float Dv = D[ed];
    float state = 0.f;

    const float* up = u     + (size_t)(b * SEQ) * DIM + ed;
    const float* dp = delta + (size_t)(b * SEQ) * DIM + ed;
    const float* bc = dbc   + (size_t)(b * SEQ) * 64;
    float*       yp = y     + (size_t)(b * SEQ) * DIM + ed;

    for (int l = 0; l < SEQ; l++) {
        float dv = dp[(size_t)l * DIM];
        float uv = up[(size_t)l * DIM];
        float Bv = bc[l * 64 + DTRANK + n];           // cols 32..47
        float Cv = bc[l * 64 + DTRANK + DSTATE + n];  // cols 48..63
        float dA = __expf(dv * Aval);
        state = state * dA + dv * Bv * uv;
        float part = state * Cv;
        part += __shfl_down_sync(0xffffffffu, part, 8, 16);
        part += __shfl_down_sync(0xffffffffu, part, 4, 16);
        part += __shfl_down_sync(0xffffffffu, part, 2, 16);
        part += __shfl_down_sync(0xffffffffu, part, 1, 16);
        if (n == 0) yp[(size_t)l * DIM] = part + Dv * uv;
    }
}

// ---------------- combine: h += (y1+y2)*silu(xz) ----------------
__global__ void combine_kernel(float* __restrict__ h, const float* __restrict__ xz,
                               const float* __restrict__ y1, const float* __restrict__ y2) {
    int idx = blockIdx.x * blockDim.x + threadIdx.x;   // < MTOK*DIM
    float z = xz[idx];
    z = z / (1.f + __expf(-z));
    h[idx] += (y1[idx] + y2[idx]) * z;
}

// ---------------- mean pool over sequence ----------------
__global__ void pool_kernel(const float* __restrict__ h, float* __restrict__ pooled) {
    int b = blockIdx.x;
    int d = blockIdx.y * blockDim.x + threadIdx.x;   // grid (16,3) x 256 -> 768
    float s = 0.f;
    const float* hp = h + (size_t)(b * SEQ) * DIM + d;
    for (int l = 0; l < SEQ; l++) s += hp[(size_t)l * DIM];
    pooled[b * DIM + d] = s * (1.f / (float)SEQ);
}

// ---------------- classification head ----------------
__global__ void head_kernel(const float* __restrict__ pin, const float* __restrict__ W,
                            const float* __restrict__ bias, float* __restrict__ out) {
    int b = blockIdx.x;
    __shared__ float sh[DIM];
    for (int i = threadIdx.x; i < DIM; i += blockDim.x) sh[i] = pin[b * DIM + i];
    __syncthreads();
    for (int cls = blockIdx.y * blockDim.x + threadIdx.x; cls < NCLS;
         cls += gridDim.y * blockDim.x) {
        float acc = bias[cls];
        for (int k = 0; k < DIM; k++) acc = fmaf(sh[k], W[(size_t)k * NCLS + cls], acc);
        out[b * NCLS + cls] = acc;
    }
}

// ---------------- launch ----------------
extern "C" void kernel_launch(void* const* d_in, const int* in_sizes, int n_in,
                              void* d_out, int out_size)
{
    const float* x        = (const float*)d_in[0];
    const float* patch_W  = (const float*)d_in[1];
    const float* patch_b  = (const float*)d_in[2];
    const float* cls_tok  = (const float*)d_in[3];
    const float* norm_g   = (const float*)d_in[4];
    const float* norm_b   = (const float*)d_in[5];
    const float* proj_W   = (const float*)d_in[6];
    const float* proj_b   = (const float*)d_in[7];
    const float* fconv_W  = (const float*)d_in[8];
    const float* fconv_b  = (const float*)d_in[9];
    const float* bconv_W  = (const float*)d_in[10];
    const float* bconv_b  = (const float*)d_in[11];
    const float* dbc_W    = (const float*)d_in[12];
    const float* dt_W     = (const float*)d_in[13];
    const float* dt_b     = (const float*)d_in[14];
    const float* A_log    = (const float*)d_in[15];
    const float* D_ssm    = (const float*)d_in[16];
    const float* head_g   = (const float*)d_in[17];
    const float* head_b   = (const float*)d_in[18];
    const float* head_W   = (const float*)d_in[19];
    const float* head_bias= (const float*)d_in[20];
    float* out = (float*)d_out;

    float *xp, *xp2, *h, *xn, *xz, *uf, *ub, *dbcf, *dbcb, *df, *db_, *y1, *y2, *pool, *pooln;
    cudaGetSymbolAddress((void**)&xp,   g_xp);
    cudaGetSymbolAddress((void**)&xp2,  g_xp2);
    cudaGetSymbolAddress((void**)&h,    g_h);
    cudaGetSymbolAddress((void**)&xn,   g_xn);
    cudaGetSymbolAddress((void**)&xz,   g_xz);
    cudaGetSymbolAddress((void**)&uf,   g_uf);
    cudaGetSymbolAddress((void**)&ub,   g_ub);
    cudaGetSymbolAddress((void**)&dbcf, g_dbcf);
    cudaGetSymbolAddress((void**)&dbcb, g_dbcb);
    cudaGetSymbolAddress((void**)&df,   g_df);
    cudaGetSymbolAddress((void**)&db_,  g_db);
    cudaGetSymbolAddress((void**)&y1,   g_y1);
    cudaGetSymbolAddress((void**)&y2,   g_y2);
    cudaGetSymbolAddress((void**)&pool, g_pool);
    cudaGetSymbolAddress((void**)&pooln,g_pooln);

    // patch embed
    patchify_kernel<<<(TPAT*DIM)/256, 256>>>(x, xp);
    gemm_kernel<128,128,8,8,8,false,0><<<dim3(DIM/128, (TPAT+127)/128), 256>>>(
        xp, DIM, patch_W, patch_b, xp2, TPAT, DIM, DIM);
    h_init_kernel<<<(MTOK*DIM)/256, 256>>>(xp2, cls_tok, h);

    for (int i = 0; i < DEPTH; i++) {
        const size_t wo = (size_t)i * DIM * DIM;
        ln_kernel<<<MTOK, 256>>>(h, xn, norm_g + i*DIM, norm_b + i*DIM);
        gemm_kernel<128,128,8,8,8,false,0><<<dim3(DIM/128, (MTOK+127)/128), 256>>>(
            xn, DIM, proj_W + wo, proj_b + i*DIM, xz, MTOK, DIM, DIM);
        // u = softplus(xz @ convW^T + convb)
        gemm_kernel<128,128,8,8,8,true,1><<<dim3(DIM/128, (MTOK+127)/128), 256>>>(
            xz, DIM, fconv_W + wo, fconv_b + i*DIM, uf, MTOK, DIM, DIM);
        gemm_kernel<128,128,8,8,8,true,1><<<dim3(DIM/128, (MTOK+127)/128), 256>>>(
            xz, DIM, bconv_W + wo, bconv_b + i*DIM, ub, MTOK, DIM, DIM);
        // dbc = u @ dbc_W   (768 -> 64), no bias / no act
        gemm_kernel<64,64,16,4,4,false,0><<<dim3(1, (MTOK+63)/64), 256>>>(
            uf, DIM, dbc_W + (size_t)i*DIM*64, nullptr, dbcf, MTOK, 64, DIM);
        gemm_kernel<64,64,16,4,4,false,0><<<dim3(1, (MTOK+63)/64), 256>>>(
            ub, DIM, dbc_W + (size_t)i*DIM*64, nullptr, dbcb, MTOK, 64, DIM);
        // delta = softplus(dt @ dt_W + dt_b)   (dt = dbc[:, :32], lda=64)
        gemm_kernel<64,64,16,4,4,false,1><<<dim3(DIM/64, (MTOK+63)/64), 256>>>(
            dbcf, 64, dt_W + (size_t)i*DTRANK*DIM, dt_b + i*DIM, df, MTOK, DIM, DTRANK);
        gemm_kernel<64,64,16,4,4,false,1><<<dim3(DIM/64, (MTOK+63)/64), 256>>>(
            dbcb, 64, dt_W + (size_t)i*DTRANK*DIM, dt_b + i*DIM, db_, MTOK, DIM, DTRANK);
        // selective scans (both forward)
        scan_kernel<<<(BATCH*DIM)/16, 256>>>(uf, df, dbcf,
            A_log + (size_t)i*DIM*DSTATE, D_ssm + i*DIM, y1);
        scan_kernel<<<(BATCH*DIM)/16, 256>>>(ub, db_, dbcb,
            A_log + (size_t)i*DIM*DSTATE, D_ssm + i*DIM, y2);
        // h = (y1+y2)*silu(xz) + h
        combine_kernel<<<(MTOK*DIM)/256, 256>>>(h, xz, y1, y2);
    }

    pool_kernel<<<dim3(BATCH, 3), 256>>>(h, pool);
    ln_kernel<<<BATCH, 256>>>(pool, pooln, head_g, head_b);
    head_kernel<<<dim3(BATCH, 4), 256>>>(pooln, head_W, head_bias, out);
}

// round 3
// speedup vs baseline: 1.6611x; 1.6611x over previous
#include <cuda_runtime.h>
#include <cuda_bf16.h>
#include <math.h>
#include <stdint.h>

typedef __nv_bfloat16 bf16;

// ---------------- problem constants ----------------
#define DIM     768
#define BATCH   16
#define SEQ     197
#define MTOK    (BATCH*SEQ)     // 3152
#define NPATCH  196
#define TPAT    (BATCH*NPATCH)  // 3136
#define DSTATE  16
#define DTRANK  32
#define NCLS    1000
#define DEPTH   12

// ---------------- static device scratch (allocation-free) ----------------
__device__ float g_h    [MTOK*DIM];
__device__ float g_xz   [MTOK*DIM];
__device__ float g_uf   [MTOK*DIM];
__device__ float g_ub   [MTOK*DIM];
__device__ float g_dbcf [MTOK*64];
__device__ float g_dbcb [MTOK*64];
__device__ float g_df   [MTOK*DIM];
__device__ float g_db   [MTOK*DIM];
__device__ float g_y1   [MTOK*DIM];
__device__ float g_y2   [MTOK*DIM];
__device__ float g_pool [BATCH*DIM];
__device__ float g_pooln[BATCH*DIM];
// bf16 split activations
__device__ bf16 g_xp0 [TPAT*DIM], g_xp1 [TPAT*DIM];
__device__ bf16 g_xn0 [MTOK*DIM], g_xn1 [MTOK*DIM];
__device__ bf16 g_xz0 [MTOK*DIM], g_xz1 [MTOK*DIM];
__device__ bf16 g_uf0 [MTOK*DIM], g_uf1 [MTOK*DIM];
__device__ bf16 g_ub0 [MTOK*DIM], g_ub1 [MTOK*DIM];
__device__ bf16 g_dtf0[MTOK*DTRANK], g_dtf1[MTOK*DTRANK];
__device__ bf16 g_dtb0[MTOK*DTRANK], g_dtb1[MTOK*DTRANK];
// bf16 split weights (stored (N,K) row-major, i.e. K-major "col" operand)
__device__ bf16 g_wproj0 [DEPTH*DIM*DIM], g_wproj1 [DEPTH*DIM*DIM];
__device__ bf16 g_wfconv0[DEPTH*DIM*DIM], g_wfconv1[DEPTH*DIM*DIM];
__device__ bf16 g_wbconv0[DEPTH*DIM*DIM], g_wbconv1[DEPTH*DIM*DIM];
__device__ bf16 g_wdbc0  [DEPTH*64*DIM],  g_wdbc1  [DEPTH*64*DIM];
__device__ bf16 g_wdt0   [DEPTH*DIM*DTRANK], g_wdt1 [DEPTH*DIM*DTRANK];
__device__ bf16 g_wpat0  [DIM*DIM],       g_wpat1  [DIM*DIM];

// ---------------- helpers ----------------
__device__ __forceinline__ float softplus_f(float x) {
    if (x > 20.f) return x;
    return log1pf(__expf(x));
}
__device__ __forceinline__ uint32_t smem_u32(const void* p) {
    uint32_t a;
    asm("{ .reg .u64 t; cvta.to.shared.u64 t, %1; cvt.u32.u64 %0, t; }" : "=r"(a) : "l"(p));
    return a;
}
__device__ __forceinline__ void cp16(uint32_t dst, const void* src, int sz) {
    asm volatile("cp.async.ca.shared.global [%0], [%1], 16, %2;"
                 :: "r"(dst), "l"(src), "r"(sz));
}
__device__ __forceinline__ void ldsm_x4(uint32_t* r, uint32_t addr) {
    asm volatile("ldmatrix.sync.aligned.m8n8.x4.shared.b16 {%0,%1,%2,%3}, [%4];"
                 : "=r"(r[0]), "=r"(r[1]), "=r"(r[2]), "=r"(r[3]) : "r"(addr));
}
__device__ __forceinline__ void mma16816(float* d, const uint32_t* a, const uint32_t* b) {
    asm volatile("mma.sync.aligned.m16n8k16.row.col.f32.bf16.bf16.f32 "
                 "{%0,%1,%2,%3}, {%4,%5,%6,%7}, {%8,%9}, {%0,%1,%2,%3};"
                 : "+f"(d[0]), "+f"(d[1]), "+f"(d[2]), "+f"(d[3])
                 : "r"(a[0]), "r"(a[1]), "r"(a[2]), "r"(a[3]), "r"(b[0]), "r"(b[1]));
}

// ---------------- weight split kernels ----------------
__global__ void split_direct_kernel(const float* __restrict__ in,
                                    bf16* __restrict__ o0, bf16* __restrict__ o1, int n) {
    int i = blockIdx.x * blockDim.x + threadIdx.x;
    if (i < n) {
        float v = in[i];
        bf16 h0 = __float2bfloat16_rn(v);
        o0[i] = h0;
        o1[i] = __float2bfloat16_rn(v - __bfloat162float(h0));
    }
}
// split + transpose: in[z] (R,C) -> out[z] (C,R)
__global__ void split_transpose_kernel(const float* __restrict__ in,
                                       bf16* __restrict__ o0, bf16* __restrict__ o1,
                                       int R, int C) {
    __shared__ float t[32][33];
    size_t off = (size_t)blockIdx.z * R * C;
    int r0 = blockIdx.y * 32, c0 = blockIdx.x * 32;
    int tx = threadIdx.x, ty = threadIdx.y;
    #pragma unroll
    for (int i = 0; i < 32; i += 8) {
        int rr = r0 + ty + i, cc = c0 + tx;
        t[ty + i][tx] = (rr < R && cc < C) ? in[off + (size_t)rr * C + cc] : 0.f;
    }
    __syncthreads();
    #pragma unroll
    for (int i = 0; i < 32; i += 8) {
        int oc = c0 + ty + i, orr = r0 + tx;
        if (oc < C && orr < R) {
            float v = t[tx][ty + i];
            bf16 h0 = __float2bfloat16_rn(v);
            o0[off + (size_t)oc * R + orr] = h0;
            o1[off + (size_t)oc * R + orr] = __float2bfloat16_rn(v - __bfloat162float(h0));
        }
    }
}

// ---------------- patchify -> bf16 splits ----------------
__global__ void patchify_split_kernel(const float* __restrict__ x,
                                      bf16* __restrict__ o0, bf16* __restrict__ o1) {
    int idx = blockIdx.x * blockDim.x + threadIdx.x;   // < TPAT*DIM
    int t = idx / DIM, f = idx % DIM;
    int b = t / NPATCH, hw = t % NPATCH;
    int hh = hw / 14, ww = hw % 14;
    int c = f % 3, pp = f / 3;
    int p1 = pp / 16, p2 = pp % 16;
    float v = x[(((size_t)(b * 3 + c) * 224) + hh * 16 + p1) * 224 + ww * 16 + p2];
    bf16 h0 = __float2bfloat16_rn(v);
    o0[idx] = h0;
    o1[idx] = __float2bfloat16_rn(v - __bfloat162float(h0));
}

__global__ void cls_init_kernel(const float* __restrict__ cls, float* __restrict__ h) {
    int idx = blockIdx.x * blockDim.x + threadIdx.x;   // < BATCH*DIM
    int b = idx / DIM, d = idx % DIM;
    h[(size_t)b * SEQ * DIM + d] = cls[d];
}

// ---------------- layernorm (optionally emitting bf16 splits) ----------------
template<bool SPLIT>
__global__ void ln_kernel(const float* __restrict__ in, float* __restrict__ outf,
                          bf16* __restrict__ o0, bf16* __restrict__ o1,
                          const float* __restrict__ g, const float* __restrict__ bv) {
    int row = blockIdx.x;
    const float* xr = in + (size_t)row * DIM;
    int tid = threadIdx.x;                  // 256 threads, 3 elems each
    float v0 = xr[tid], v1 = xr[tid + 256], v2 = xr[tid + 512];
    __shared__ float red[256];
    red[tid] = v0 + v1 + v2;
    __syncthreads();
    #pragma unroll
    for (int o = 128; o > 0; o >>= 1) { if (tid < o) red[tid] += red[tid + o]; __syncthreads(); }
    float mean = red[0] * (1.f / 768.f);
    __syncthreads();
    float d0 = v0 - mean, d1 = v1 - mean, d2 = v2 - mean;
    red[tid] = d0 * d0 + d1 * d1 + d2 * d2;
    __syncthreads();
    #pragma unroll
    for (int o = 128; o > 0; o >>= 1) { if (tid < o) red[tid] += red[tid + o]; __syncthreads(); }
    float rstd = rsqrtf(red[0] * (1.f / 768.f) + 1e-5f);
    float r0 = d0 * rstd * g[tid]       + bv[tid];
    float r1 = d1 * rstd * g[tid + 256] + bv[tid + 256];
    float r2 = d2 * rstd * g[tid + 512] + bv[tid + 512];
    if (SPLIT) {
        size_t base = (size_t)row * DIM;
        bf16 h0;
        h0 = __float2bfloat16_rn(r0); o0[base + tid]       = h0; o1[base + tid]       = __float2bfloat16_rn(r0 - __bfloat162float(h0));
        h0 = __float2bfloat16_rn(r1); o0[base + tid + 256] = h0; o1[base + tid + 256] = __float2bfloat16_rn(r1 - __bfloat162float(h0));
        h0 = __float2bfloat16_rn(r2); o0[base + tid + 512] = h0; o1[base + tid + 512] = __float2bfloat16_rn(r2 - __bfloat162float(h0));
    } else {
        float* orow = outf + (size_t)row * DIM;
        orow[tid] = r0; orow[tid + 256] = r1; orow[tid + 512] = r2;
    }
}

// ---------------- warp-MMA GEMM (mma.sync bf16, 3-term compensated) ----------------
// C[M,N] = act( [A0+A1][M,K] * ([B0+B1][N,K])^T + bias )
// A row-major (lda), B stored (N,K) row-major (= col-major KxN operand).
// Optional split output C0/C1 for first split_cols columns.
// REMAP: C row index = m + m/196 + 1  (patch -> h placement).
template<int NT, int ACT, bool REMAP>
__global__ void __launch_bounds__(256)
mma_gemm_kernel(const bf16* __restrict__ A0, const bf16* __restrict__ A1, int lda,
                const bf16* __restrict__ B0, const bf16* __restrict__ B1, int ldb,
                const float* __restrict__ bias,
                float* __restrict__ C, int ldc,
                bf16* __restrict__ C0, bf16* __restrict__ C1, int split_cols,
                int M, int N, int K)
{
    constexpr int BM = 128, BK = 32;
    constexpr int WGM = (NT == 128) ? 2 : 4;     // warps along M
    constexpr int WGN = 8 / WGM;                 // warps along N
    constexpr int WM = BM / WGM;                 // 64 or 32
    constexpr int WN = NT / WGN;                 // 32
    constexpr int MT = WM / 16;                  // 4 or 2
    constexpr int NTL = WN / 8;                  // 4
    constexpr int RS = 80;                       // padded row stride (bytes)
    constexpr int TA = BM * RS;                  // one A tile
    constexpr int TB = NT * RS;                  // one B tile
    constexpr int STAGE = 2 * TA + 2 * TB;       // a0,a1,b0,b1

    extern __shared__ char smem[];
    uint32_t sb = smem_u32(smem);
    int tid = threadIdx.x, wid = tid >> 5, lane = tid & 31;
    int n0 = blockIdx.x * NT, m0 = blockIdx.y * BM;
    int wm = wid & (WGM - 1), wn = wid / WGM;
    int mBase = wm * WM, nBase = wn * WN;

    const int nch = K >> 5;   // K is a multiple of 32 in all call sites

    auto load_stage = [&](int c) {
        uint32_t base = sb + (uint32_t)(c & 1) * STAGE;
        int k0 = c << 5;
        // A tiles: BM rows x 4 16B-chunks, 2 splits
        for (int u = tid; u < BM * 4; u += 256) {
            int r = u >> 2, c16 = u & 3;
            int gr = m0 + r;
            const bf16* s0 = A0 + (size_t)gr * lda + k0 + c16 * 8;
            const bf16* s1 = A1 + (size_t)gr * lda + k0 + c16 * 8;
            int sz = (gr < M) ? 16 : 0;
            uint32_t d = base + r * RS + c16 * 16;
            cp16(d, s0, sz);
            cp16(d + TA, s1, sz);
        }
        // B tiles: NT rows x 4 chunks, 2 splits
        for (int u = tid; u < NT * 4; u += 256) {
            int r = u >> 2, c16 = u & 3;
            int gr = n0 + r;
            const bf16* s0 = B0 + (size_t)gr * ldb + k0 + c16 * 8;
            const bf16* s1 = B1 + (size_t)gr * ldb + k0 + c16 * 8;
            int sz = (gr < N) ? 16 : 0;
            uint32_t d = base + 2 * TA + r * RS + c16 * 16;
            cp16(d, s0, sz);
            cp16(d + TB, s1, sz);
        }
        asm volatile("cp.async.commit_group;" ::: "memory");
    };

    float acc[MT][NTL][4];
    #pragma unroll
    for (int i = 0; i < MT; i++)
        #pragma unroll
        for (int j = 0; j < NTL; j++)
            #pragma unroll
            for (int e = 0; e < 4; e++) acc[i][j][e] = 0.f;

    load_stage(0);

    for (int c = 0; c < nch; c++) {
        if (c + 1 < nch) {
            load_stage(c + 1);
            asm volatile("cp.async.wait_group 1;" ::: "memory");
        } else {
            asm volatile("cp.async.wait_group 0;" ::: "memory");
        }
        __syncthreads();

        uint32_t sA0 = sb + (uint32_t)(c & 1) * STAGE;
        uint32_t sA1 = sA0 + TA;
        uint32_t sB0 = sA0 + 2 * TA;
        uint32_t sB1 = sB0 + TB;

        #pragma unroll
        for (int kk = 0; kk < BK; kk += 16) {
            uint32_t a0f[MT][4], a1f[MT][4];
            #pragma unroll
            for (int mi = 0; mi < MT; mi++) {
                int row = mBase + mi * 16 + (lane & 15);
                int kc = kk + ((lane >> 4) << 3);
                uint32_t off = (uint32_t)(row * RS + kc * 2);
                ldsm_x4(a0f[mi], sA0 + off);
                ldsm_x4(a1f[mi], sA1 + off);
            }
            uint32_t b0f[NTL / 2][4], b1f[NTL / 2][4];
            #pragma unroll
            for (int bi = 0; bi < NTL / 2; bi++) {
                int row = nBase + bi * 16 + (lane & 7) + ((lane >> 4) << 3);
                int kc = kk + (((lane >> 3) & 1) << 3);
                uint32_t off = (uint32_t)(row * RS + kc * 2);
                ldsm_x4(b0f[bi], sB0 + off);
                ldsm_x4(b1f[bi], sB1 + off);
            }
            #pragma unroll
            for (int mi = 0; mi < MT; mi++)
                #pragma unroll
                for (int ni = 0; ni < NTL; ni++) {
                    const uint32_t* bb0 = &b0f[ni >> 1][(ni & 1) * 2];
                    const uint32_t* bb1 = &b1f[ni >> 1][(ni & 1) * 2];
                    mma16816(acc[mi][ni], a0f[mi], bb0);
                    mma16816(acc[mi][ni], a0f[mi], bb1);
                    mma16816(acc[mi][ni], a1f[mi], bb0);
                }
        }
        __syncthreads();
    }

    // ---- epilogue ----
    #pragma unroll
    for (int mi = 0; mi < MT; mi++) {
        #pragma unroll
        for (int e = 0; e < 4; e++) {
            int m = m0 + mBase + mi * 16 + (lane >> 2) + ((e >> 1) << 3);
            if (m >= M) continue;
            int row = REMAP ? (m + m / 196 + 1) : m;
            float* crow = C + (size_t)row * ldc;
            #pragma unroll
            for (int ni = 0; ni < NTL; ni++) {
                int n = n0 + nBase + ni * 8 + (lane & 3) * 2 + (e & 1);
                float v = acc[mi][ni][e];
                if (bias) v += __ldg(bias + n);
                if (ACT == 1) v = softplus_f(v);
                crow[n] = v;
                if (C0 != nullptr && n < split_cols) {
                    bf16 h0 = __float2bfloat16_rn(v);
                    C0[(size_t)m * split_cols + n] = h0;
                    C1[(size_t)m * split_cols + n] = __float2bfloat16_rn(v - __bfloat162float(h0));
                }
            }
        }
    }
}

// ---------------- selective scan ----------------
__global__ void __launch_bounds__(256)
scan_kernel(const float* __restrict__ u, const float* __restrict__ delta,
            const float* __restrict__ dbc, const float* __restrict__ A_log,
            const float* __restrict__ D, float* __restrict__ y)
{
    int g = blockIdx.x * 16 + (threadIdx.x >> 4);   // (b*768+ed)
    int n = threadIdx.x & 15;
    int b = g / DIM;
    int ed = g % DIM;

    float Aval = -__expf(A_log[ed * DSTATE + n]);
    float Dv = D[ed];
    float state = 0.f;

    const float* up = u     + (size_t)(b * SEQ) * DIM + ed;
    const float* dp = delta + (size_t)(b * SEQ) * DIM + ed;
    const float* bc = dbc   + (size_t)(b * SEQ) * 64;
    float*       yp = y     + (size_t)(b * SEQ) * DIM + ed;

    for (int l = 0; l < SEQ; l++) {
        float dv = dp[(size_t)l * DIM];
        float uv = up[(size_t)l * DIM];
        float Bv = bc[l * 64 + DTRANK + n];
        float Cv = bc[l * 64 + DTRANK + DSTATE + n];
        float dA = __expf(dv * Aval);
        state = state * dA + dv * Bv * uv;
        float part = state * Cv;
        part += __shfl_down_sync(0xffffffffu, part, 8, 16);
        part += __shfl_down_sync(0xffffffffu, part, 4, 16);
        part += __shfl_down_sync(0xffffffffu, part, 2, 16);
        part += __shfl_down_sync(0xffffffffu, part, 1, 16);
        if (n == 0) yp[(size_t)l * DIM] = part + Dv * uv;
    }
}

// ---------------- combine: h += (y1+y2)*silu(xz) ----------------
__global__ void combine_kernel(float* __restrict__ h, const float* __restrict__ xz,
                               const float* __restrict__ y1, const float* __restrict__ y2) {
    int idx = blockIdx.x * blockDim.x + threadIdx.x;
    float z = xz[idx];
    z = z / (1.f + __expf(-z));
    h[idx] += (y1[idx] + y2[idx]) * z;
}

// ---------------- mean pool over sequence ----------------
__global__ void pool_kernel(const float* __restrict__ h, float* __restrict__ pooled) {
    int b = blockIdx.x;
    int d = blockIdx.y * blockDim.x + threadIdx.x;
    float s = 0.f;
    const float* hp = h + (size_t)(b * SEQ) * DIM + d;
    for (int l = 0; l < SEQ; l++) s += hp[(size_t)l * DIM];
    pooled[b * DIM + d] = s * (1.f / (float)SEQ);
}

// ---------------- classification head ----------------
__global__ void head_kernel(const float* __restrict__ pin, const float* __restrict__ W,
                            const float* __restrict__ bias, float* __restrict__ out) {
    int b = blockIdx.x;
    __shared__ float sh[DIM];
    for (int i = threadIdx.x; i < DIM; i += blockDim.x) sh[i] = pin[b * DIM + i];
    __syncthreads();
    for (int cls = blockIdx.y * blockDim.x + threadIdx.x; cls < NCLS;
         cls += gridDim.y * blockDim.x) {
        float acc = bias[cls];
        for (int k = 0; k < DIM; k++) acc = fmaf(sh[k], W[(size_t)k * NCLS + cls], acc);
        out[b * NCLS + cls] = acc;
    }
}

// ---------------- launch ----------------
extern "C" void kernel_launch(void* const* d_in, const int* in_sizes, int n_in,
                              void* d_out, int out_size)
{
    const float* x        = (const float*)d_in[0];
    const float* patch_W  = (const float*)d_in[1];
    const float* patch_b  = (const float*)d_in[2];
    const float* cls_tok  = (const float*)d_in[3];
    const float* norm_g   = (const float*)d_in[4];
    const float* norm_b   = (const float*)d_in[5];
    const float* proj_W   = (const float*)d_in[6];
    const float* proj_b   = (const float*)d_in[7];
    const float* fconv_W  = (const float*)d_in[8];
    const float* fconv_b  = (const float*)d_in[9];
    const float* bconv_W  = (const float*)d_in[10];
    const float* bconv_b  = (const float*)d_in[11];
    const float* dbc_W    = (const float*)d_in[12];
    const float* dt_W     = (const float*)d_in[13];
    const float* dt_b     = (const float*)d_in[14];
    const float* A_log    = (const float*)d_in[15];
    const float* D_ssm    = (const float*)d_in[16];
    const float* head_g   = (const float*)d_in[17];
    const float* head_b   = (const float*)d_in[18];
    const float* head_W   = (const float*)d_in[19];
    const float* head_bias= (const float*)d_in[20];
    float* out = (float*)d_out;

    float *h, *xz, *uf, *ub, *dbcf, *dbcb, *df, *db_, *y1, *y2, *pool, *pooln;
    cudaGetSymbolAddress((void**)&h,    g_h);
    cudaGetSymbolAddress((void**)&xz,   g_xz);
    cudaGetSymbolAddress((void**)&uf,   g_uf);
    cudaGetSymbolAddress((void**)&ub,   g_ub);
    cudaGetSymbolAddress((void**)&dbcf, g_dbcf);
    cudaGetSymbolAddress((void**)&dbcb, g_dbcb);
    cudaGetSymbolAddress((void**)&df,   g_df);
    cudaGetSymbolAddress((void**)&db_,  g_db);
    cudaGetSymbolAddress((void**)&y1,   g_y1);
    cudaGetSymbolAddress((void**)&y2,   g_y2);
    cudaGetSymbolAddress((void**)&pool, g_pool);
    cudaGetSymbolAddress((void**)&pooln,g_pooln);
    bf16 *xp0,*xp1,*xn0,*xn1,*xz0,*xz1,*uf0,*uf1,*ub0,*ub1,*dtf0,*dtf1,*dtb0,*dtb1;
    cudaGetSymbolAddress((void**)&xp0, g_xp0);  cudaGetSymbolAddress((void**)&xp1, g_xp1);
    cudaGetSymbolAddress((void**)&xn0, g_xn0);  cudaGetSymbolAddress((void**)&xn1, g_xn1);
    cudaGetSymbolAddress((void**)&xz0, g_xz0);  cudaGetSymbolAddress((void**)&xz1, g_xz1);
    cudaGetSymbolAddress((void**)&uf0, g_uf0);  cudaGetSymbolAddress((void**)&uf1, g_uf1);
    cudaGetSymbolAddress((void**)&ub0, g_ub0);  cudaGetSymbolAddress((void**)&ub1, g_ub1);
    cudaGetSymbolAddress((void**)&dtf0,g_dtf0); cudaGetSymbolAddress((void**)&dtf1,g_dtf1);
    cudaGetSymbolAddress((void**)&dtb0,g_dtb0); cudaGetSymbolAddress((void**)&dtb1,g_dtb1);
    bf16 *wp0,*wp1,*wf0,*wf1,*wb0,*wb1,*wd0,*wd1,*wt0,*wt1,*wa0,*wa1;
    cudaGetSymbolAddress((void**)&wp0, g_wproj0);  cudaGetSymbolAddress((void**)&wp1, g_wproj1);
    cudaGetSymbolAddress((void**)&wf0, g_wfconv0); cudaGetSymbolAddress((void**)&wf1, g_wfconv1);
    cudaGetSymbolAddress((void**)&wb0, g_wbconv0); cudaGetSymbolAddress((void**)&wb1, g_wbconv1);
    cudaGetSymbolAddress((void**)&wd0, g_wdbc0);   cudaGetSymbolAddress((void**)&wd1, g_wdbc1);
    cudaGetSymbolAddress((void**)&wt0, g_wdt0);    cudaGetSymbolAddress((void**)&wt1, g_wdt1);
    cudaGetSymbolAddress((void**)&wa0, g_wpat0);   cudaGetSymbolAddress((void**)&wa1, g_wpat1);

    // smem sizes: 2 stages * (2*A_tile + 2*B_tile), rows padded to 80B
    const int SMEM_BIG   = 2 * (2 * 128 * 80 + 2 * 128 * 80);  // 81920
    const int SMEM_SMALL = 2 * (2 * 128 * 80 + 2 *  64 * 80);  // 61440
    cudaFuncSetAttribute(mma_gemm_kernel<128,0,false>, cudaFuncAttributeMaxDynamicSharedMemorySize, SMEM_BIG);
    cudaFuncSetAttribute(mma_gemm_kernel<128,0,true >, cudaFuncAttributeMaxDynamicSharedMemorySize, SMEM_BIG);
    cudaFuncSetAttribute(mma_gemm_kernel<128,1,false>, cudaFuncAttributeMaxDynamicSharedMemorySize, SMEM_BIG);
    cudaFuncSetAttribute(mma_gemm_kernel<64 ,0,false>, cudaFuncAttributeMaxDynamicSharedMemorySize, SMEM_SMALL);

    const dim3 gBig(DIM / 128, (MTOK + 127) / 128);   // (6, 25)
    const dim3 gPat(DIM / 128, (TPAT + 127) / 128);   // (6, 25)
    const dim3 gDbc(1, (MTOK + 127) / 128);           // (1, 25)

    // ---- weight conversions ----
    {
        int n = DEPTH * DIM * DIM;
        split_direct_kernel<<<(n + 255) / 256, 256>>>(fconv_W, wf0, wf1, n);
        split_direct_kernel<<<(n + 255) / 256, 256>>>(bconv_W, wb0, wb1, n);
        dim3 blk(32, 8);
        split_transpose_kernel<<<dim3(24, 24, DEPTH), blk>>>(proj_W, wp0, wp1, DIM, DIM);
        split_transpose_kernel<<<dim3(2, 24, DEPTH), blk>>>(dbc_W, wd0, wd1, DIM, 64);
        split_transpose_kernel<<<dim3(24, 1, DEPTH), blk>>>(dt_W, wt0, wt1, DTRANK, DIM);
        split_transpose_kernel<<<dim3(24, 24, 1), blk>>>(patch_W, wa0, wa1, DIM, DIM);
    }

    // ---- patch embed ----
    patchify_split_kernel<<<(TPAT * DIM) / 256, 256>>>(x, xp0, xp1);
    cls_init_kernel<<<(BATCH * DIM) / 256, 256>>>(cls_tok, h);
    mma_gemm_kernel<128,0,true><<<gPat, 256, SMEM_BIG>>>(
        xp0, xp1, DIM, wa0, wa1, DIM, patch_b, h, DIM,
        nullptr, nullptr, 0, TPAT, DIM, DIM);

    for (int i = 0; i < DEPTH; i++) {
        const size_t wo = (size_t)i * DIM * DIM;
        ln_kernel<true><<<MTOK, 256>>>(h, nullptr, xn0, xn1, norm_g + i*DIM, norm_b + i*DIM);
        // xz = xn @ proj_W + proj_b   (+ splits)
        mma_gemm_kernel<128,0,false><<<gBig, 256, SMEM_BIG>>>(
            xn0, xn1, DIM, wp0 + wo, wp1 + wo, DIM, proj_b + i*DIM,
            xz, DIM, xz0, xz1, DIM, MTOK, DIM, DIM);
        // u = softplus(xz @ convW^T + convb)   (+ splits)
        mma_gemm_kernel<128,1,false><<<gBig, 256, SMEM_BIG>>>(
            xz0, xz1, DIM, wf0 + wo, wf1 + wo, DIM, fconv_b + i*DIM,
            uf, DIM, uf0, uf1, DIM, MTOK, DIM, DIM);
        mma_gemm_kernel<128,1,false><<<gBig, 256, SMEM_BIG>>>(
            xz0, xz1, DIM, wb0 + wo, wb1 + wo, DIM, bconv_b + i*DIM,
            ub, DIM, ub0, ub1, DIM, MTOK, DIM, DIM);
        // dbc = u @ dbc_W   (M x 64; split first 32 cols = dt input)
        mma_gemm_kernel<64,0,false><<<gDbc, 256, SMEM_SMALL>>>(
            uf0, uf1, DIM, wd0 + (size_t)i*64*DIM, wd1 + (size_t)i*64*DIM, DIM, nullptr,
            dbcf, 64, dtf0, dtf1, DTRANK, MTOK, 64, DIM);
        mma_gemm_kernel<64,0,false><<<gDbc, 256, SMEM_SMALL>>>(
            ub0, ub1, DIM, wd0 + (size_t)i*64*DIM, wd1 + (size_t)i*64*DIM, DIM, nullptr,
            dbcb, 64, dtb0, dtb1, DTRANK, MTOK, 64, DIM);
        // delta = softplus(dt @ dt_W + dt_b)
        mma_gemm_kernel<128,1,false><<<gBig, 256, SMEM_BIG>>>(
            dtf0, dtf1, DTRANK, wt0 + (size_t)i*DIM*DTRANK, wt1 + (size_t)i*DIM*DTRANK, DTRANK,
            dt_b + i*DIM, df, DIM, nullptr, nullptr, 0, MTOK, DIM, DTRANK);
        mma_gemm_kernel<128,1,false><<<gBig, 256, SMEM_BIG>>>(
            dtb0, dtb1, DTRANK, wt0 + (size_t)i*DIM*DTRANK, wt1 + (size_t)i*DIM*DTRANK, DTRANK,
            dt_b + i*DIM, db_, DIM, nullptr, nullptr, 0, MTOK, DIM, DTRANK);
        // selective scans (both directions are forward scans in the reference)
        scan_kernel<<<(BATCH * DIM) / 16, 256>>>(uf, df, dbcf,
            A_log + (size_t)i*DIM*DSTATE, D_ssm + i*DIM, y1);
        scan_kernel<<<(BATCH * DIM) / 16, 256>>>(ub, db_, dbcb,
            A_log + (size_t)i*DIM*DSTATE, D_ssm + i*DIM, y2);
        combine_kernel<<<(MTOK * DIM) / 256, 256>>>(h, xz, y1, y2);
    }

    pool_kernel<<<dim3(BATCH, 3), 256>>>(h, pool);
    ln_kernel<false><<<BATCH, 256>>>(pool, pooln, nullptr, nullptr, head_g, head_b);
    head_kernel<<<dim3(BATCH, 4), 256>>>(pooln, head_W, head_bias, out);
}

// round 5
// speedup vs baseline: 2.0191x; 1.2155x over previous
#include <cuda_runtime.h>
#include <cuda_bf16.h>
#include <math.h>
#include <stdint.h>

typedef __nv_bfloat16 bf16;

// ---------------- problem constants ----------------
#define DIM     768
#define BATCH   16
#define SEQ     197
#define MTOK    (BATCH*SEQ)     // 3152
#define NPATCH  196
#define TPAT    (BATCH*NPATCH)  // 3136
#define DSTATE  16
#define DTRANK  32
#define NCLS    1000
#define DEPTH   12

// ---------------- static device scratch (allocation-free) ----------------
__device__ float g_h    [MTOK*DIM];
__device__ float g_xz   [MTOK*DIM];
__device__ float g_uf   [MTOK*DIM];
__device__ float g_ub   [MTOK*DIM];
__device__ float g_dbcf [MTOK*64];
__device__ float g_dbcb [MTOK*64];
__device__ float g_df   [MTOK*DIM];
__device__ float g_db   [MTOK*DIM];
__device__ float g_y1   [MTOK*DIM];
__device__ float g_y2   [MTOK*DIM];
__device__ float g_pool [BATCH*DIM];
__device__ float g_pooln[BATCH*DIM];
// bf16 split activations
__device__ bf16 g_xp0 [TPAT*DIM], g_xp1 [TPAT*DIM];
__device__ bf16 g_xn0 [MTOK*DIM], g_xn1 [MTOK*DIM];
__device__ bf16 g_xz0 [MTOK*DIM], g_xz1 [MTOK*DIM];
__device__ bf16 g_uf0 [MTOK*DIM], g_uf1 [MTOK*DIM];
__device__ bf16 g_ub0 [MTOK*DIM], g_ub1 [MTOK*DIM];
__device__ bf16 g_dtf0[MTOK*DTRANK], g_dtf1[MTOK*DTRANK];
__device__ bf16 g_dtb0[MTOK*DTRANK], g_dtb1[MTOK*DTRANK];
// bf16 split weights (stored (N,K) row-major = K-major "col" operand)
__device__ bf16 g_wproj0 [DEPTH*DIM*DIM], g_wproj1 [DEPTH*DIM*DIM];
__device__ bf16 g_wfconv0[DEPTH*DIM*DIM], g_wfconv1[DEPTH*DIM*DIM];
__device__ bf16 g_wbconv0[DEPTH*DIM*DIM], g_wbconv1[DEPTH*DIM*DIM];
__device__ bf16 g_wdbc0  [DEPTH*64*DIM],  g_wdbc1  [DEPTH*64*DIM];
__device__ bf16 g_wdt0   [DEPTH*DIM*DTRANK], g_wdt1 [DEPTH*DIM*DTRANK];
__device__ bf16 g_wpat0  [DIM*DIM],       g_wpat1  [DIM*DIM];

// ---------------- helpers ----------------
__device__ __forceinline__ float softplus_f(float x) {
    if (x > 20.f) return x;
    return log1pf(__expf(x));
}
__device__ __forceinline__ uint32_t smem_u32(const void* p) {
    uint32_t a;
    asm("{ .reg .u64 t; cvta.to.shared.u64 t, %1; cvt.u32.u64 %0, t; }" : "=r"(a) : "l"(p));
    return a;
}
__device__ __forceinline__ void cp16(uint32_t dst, const void* src, int sz) {
    asm volatile("cp.async.ca.shared.global [%0], [%1], 16, %2;"
                 :: "r"(dst), "l"(src), "r"(sz));
}
__device__ __forceinline__ void ldsm_x4(uint32_t* r, uint32_t addr) {
    asm volatile("ldmatrix.sync.aligned.m8n8.x4.shared.b16 {%0,%1,%2,%3}, [%4];"
                 : "=r"(r[0]), "=r"(r[1]), "=r"(r[2]), "=r"(r[3]) : "r"(addr));
}
__device__ __forceinline__ void mma16816(float* d, const uint32_t* a, const uint32_t* b) {
    asm volatile("mma.sync.aligned.m16n8k16.row.col.f32.bf16.bf16.f32 "
                 "{%0,%1,%2,%3}, {%4,%5,%6,%7}, {%8,%9}, {%0,%1,%2,%3};"
                 : "+f"(d[0]), "+f"(d[1]), "+f"(d[2]), "+f"(d[3])
                 : "r"(a[0]), "r"(a[1]), "r"(a[2]), "r"(a[3]), "r"(b[0]), "r"(b[1]));
}

// ---------------- weight split kernels ----------------
__global__ void split_direct_kernel(const float* __restrict__ in,
                                    bf16* __restrict__ o0, bf16* __restrict__ o1, int n) {
    int i = blockIdx.x * blockDim.x + threadIdx.x;
    if (i < n) {
        float v = in[i];
        bf16 h0 = __float2bfloat16_rn(v);
        o0[i] = h0;
        o1[i] = __float2bfloat16_rn(v - __bfloat162float(h0));
    }
}
// split + transpose: in[z] (R,C) -> out[z] (C,R)
__global__ void split_transpose_kernel(const float* __restrict__ in,
                                       bf16* __restrict__ o0, bf16* __restrict__ o1,
                                       int R, int C) {
    __shared__ float t[32][33];
    size_t off = (size_t)blockIdx.z * R * C;
    int r0 = blockIdx.y * 32, c0 = blockIdx.x * 32;
    int tx = threadIdx.x, ty = threadIdx.y;
    #pragma unroll
    for (int i = 0; i < 32; i += 8) {
        int rr = r0 + ty + i, cc = c0 + tx;
        t[ty + i][tx] = (rr < R && cc < C) ? in[off + (size_t)rr * C + cc] : 0.f;
    }
    __syncthreads();
    #pragma unroll
    for (int i = 0; i < 32; i += 8) {
        int oc = c0 + ty + i, orr = r0 + tx;
        if (oc < C && orr < R) {
            float v = t[tx][ty + i];
            bf16 h0 = __float2bfloat16_rn(v);
            o0[off + (size_t)oc * R + orr] = h0;
            o1[off + (size_t)oc * R + orr] = __float2bfloat16_rn(v - __bfloat162float(h0));
        }
    }
}

// ---------------- patchify -> bf16 splits ----------------
__global__ void patchify_split_kernel(const float* __restrict__ x,
                                      bf16* __restrict__ o0, bf16* __restrict__ o1) {
    int idx = blockIdx.x * blockDim.x + threadIdx.x;   // < TPAT*DIM
    int t = idx / DIM, f = idx % DIM;
    int b = t / NPATCH, hw = t % NPATCH;
    int hh = hw / 14, ww = hw % 14;
    int c = f % 3, pp = f / 3;
    int p1 = pp / 16, p2 = pp % 16;
    float v = x[(((size_t)(b * 3 + c) * 224) + hh * 16 + p1) * 224 + ww * 16 + p2];
    bf16 h0 = __float2bfloat16_rn(v);
    o0[idx] = h0;
    o1[idx] = __float2bfloat16_rn(v - __bfloat162float(h0));
}

__global__ void cls_init_kernel(const float* __restrict__ cls, float* __restrict__ h) {
    int idx = blockIdx.x * blockDim.x + threadIdx.x;   // < BATCH*DIM
    int b = idx / DIM, d = idx % DIM;
    h[(size_t)b * SEQ * DIM + d] = cls[d];
}

// ---------------- layernorm (optionally emitting bf16 splits) ----------------
template<bool SPLIT>
__global__ void ln_kernel(const float* __restrict__ in, float* __restrict__ outf,
                          bf16* __restrict__ o0, bf16* __restrict__ o1,
                          const float* __restrict__ g, const float* __restrict__ bv) {
    int row = blockIdx.x;
    const float* xr = in + (size_t)row * DIM;
    int tid = threadIdx.x;
    float v0 = xr[tid], v1 = xr[tid + 256], v2 = xr[tid + 512];
    __shared__ float red[256];
    red[tid] = v0 + v1 + v2;
    __syncthreads();
    #pragma unroll
    for (int o = 128; o > 0; o >>= 1) { if (tid < o) red[tid] += red[tid + o]; __syncthreads(); }
    float mean = red[0] * (1.f / 768.f);
    __syncthreads();
    float d0 = v0 - mean, d1 = v1 - mean, d2 = v2 - mean;
    red[tid] = d0 * d0 + d1 * d1 + d2 * d2;
    __syncthreads();
    #pragma unroll
    for (int o = 128; o > 0; o >>= 1) { if (tid < o) red[tid] += red[tid + o]; __syncthreads(); }
    float rstd = rsqrtf(red[0] * (1.f / 768.f) + 1e-5f);
    float r0 = d0 * rstd * g[tid]       + bv[tid];
    float r1 = d1 * rstd * g[tid + 256] + bv[tid + 256];
    float r2 = d2 * rstd * g[tid + 512] + bv[tid + 512];
    if (SPLIT) {
        size_t base = (size_t)row * DIM;
        bf16 h0;
        h0 = __float2bfloat16_rn(r0); o0[base + tid]       = h0; o1[base + tid]       = __float2bfloat16_rn(r0 - __bfloat162float(h0));
        h0 = __float2bfloat16_rn(r1); o0[base + tid + 256] = h0; o1[base + tid + 256] = __float2bfloat16_rn(r1 - __bfloat162float(h0));
        h0 = __float2bfloat16_rn(r2); o0[base + tid + 512] = h0; o1[base + tid + 512] = __float2bfloat16_rn(r2 - __bfloat162float(h0));
    } else {
        float* orow = outf + (size_t)row * DIM;
        orow[tid] = r0; orow[tid + 256] = r1; orow[tid + 512] = r2;
    }
}

// ---------------- fused combine + layernorm + split ----------------
// h = h + (y1+y2)*silu(xz); then LN(h) -> bf16 splits for next layer
__global__ void combine_ln_kernel(float* __restrict__ h, const float* __restrict__ xz,
                                  const float* __restrict__ y1, const float* __restrict__ y2,
                                  const float* __restrict__ g, const float* __restrict__ bv,
                                  bf16* __restrict__ o0, bf16* __restrict__ o1) {
    int row = blockIdx.x;
    int tid = threadIdx.x;
    size_t base = (size_t)row * DIM;
    float v[3];
    #pragma unroll
    for (int e = 0; e < 3; e++) {
        size_t idx = base + tid + e * 256;
        float z = xz[idx];
        z = z / (1.f + __expf(-z));
        float val = h[idx] + (y1[idx] + y2[idx]) * z;
        h[idx] = val;
        v[e] = val;
    }
    __shared__ float red[256];
    red[tid] = v[0] + v[1] + v[2];
    __syncthreads();
    #pragma unroll
    for (int o = 128; o > 0; o >>= 1) { if (tid < o) red[tid] += red[tid + o]; __syncthreads(); }
    float mean = red[0] * (1.f / 768.f);
    __syncthreads();
    float d0 = v[0] - mean, d1 = v[1] - mean, d2 = v[2] - mean;
    red[tid] = d0 * d0 + d1 * d1 + d2 * d2;
    __syncthreads();
    #pragma unroll
    for (int o = 128; o > 0; o >>= 1) { if (tid < o) red[tid] += red[tid + o]; __syncthreads(); }
    float rstd = rsqrtf(red[0] * (1.f / 768.f) + 1e-5f);
    float r0 = d0 * rstd * g[tid]       + bv[tid];
    float r1 = d1 * rstd * g[tid + 256] + bv[tid + 256];
    float r2 = d2 * rstd * g[tid + 512] + bv[tid + 512];
    bf16 h0;
    h0 = __float2bfloat16_rn(r0); o0[base + tid]       = h0; o1[base + tid]       = __float2bfloat16_rn(r0 - __bfloat162float(h0));
    h0 = __float2bfloat16_rn(r1); o0[base + tid + 256] = h0; o1[base + tid + 256] = __float2bfloat16_rn(r1 - __bfloat162float(h0));
    h0 = __float2bfloat16_rn(r2); o0[base + tid + 512] = h0; o1[base + tid + 512] = __float2bfloat16_rn(r2 - __bfloat162float(h0));
}

// ---------------- fused final combine + mean pool ----------------
__global__ void combine_pool_kernel(const float* __restrict__ h, const float* __restrict__ xz,
                                    const float* __restrict__ y1, const float* __restrict__ y2,
                                    float* __restrict__ pooled) {
    int b = blockIdx.x;
    int d = blockIdx.y * blockDim.x + threadIdx.x;   // grid (16,3) x 256
    float s = 0.f;
    size_t base = (size_t)(b * SEQ) * DIM + d;
    for (int l = 0; l < SEQ; l++) {
        size_t idx = base + (size_t)l * DIM;
        float z = xz[idx];
        z = z / (1.f + __expf(-z));
        s += h[idx] + (y1[idx] + y2[idx]) * z;
    }
    pooled[b * DIM + d] = s * (1.f / (float)SEQ);
}

// ---------------- warp-MMA GEMM (mma.sync bf16, 3-term compensated) ----------------
struct GemmArgs {
    const bf16 *A0, *A1; int lda;
    const bf16 *B0, *B1; int ldb;
    const float* bias;
    float* C; int ldc;
    bf16 *C0, *C1; int split_cols;
    int M, N, K;
};

template<int BM, int NT, int ACT, bool REMAP>
__global__ void __launch_bounds__(256)
mma_gemm_kernel(GemmArgs pa, GemmArgs pb)
{
    const GemmArgs P = (blockIdx.z == 0) ? pa : pb;
    constexpr int BK = 32;
    constexpr int WGM = (NT == 128) ? 2 : 4;
    constexpr int WGN = 8 / WGM;
    constexpr int WM = BM / WGM;
    constexpr int WN = NT / WGN;
    constexpr int MT = WM / 16;
    constexpr int NTL = WN / 8;
    constexpr int RS = 80;
    constexpr int TA = BM * RS;
    constexpr int TB = NT * RS;
    constexpr int STAGE = 2 * TA + 2 * TB;

    extern __shared__ char smem[];
    uint32_t sb = smem_u32(smem);
    int tid = threadIdx.x, wid = tid >> 5, lane = tid & 31;
    int n0 = blockIdx.x * NT, m0 = blockIdx.y * BM;
    int wm = wid & (WGM - 1), wn = wid / WGM;
    int mBase = wm * WM, nBase = wn * WN;

    const int nch = P.K >> 5;

    auto load_stage = [&](int c) {
        uint32_t base = sb + (uint32_t)(c & 1) * STAGE;
        int k0 = c << 5;
        for (int u = tid; u < BM * 4; u += 256) {
            int r = u >> 2, c16 = u & 3;
            int gr = m0 + r;
            const bf16* s0 = P.A0 + (size_t)gr * P.lda + k0 + c16 * 8;
            const bf16* s1 = P.A1 + (size_t)gr * P.lda + k0 + c16 * 8;
            int sz = (gr < P.M) ? 16 : 0;
            uint32_t d = base + r * RS + c16 * 16;
            cp16(d, s0, sz);
            cp16(d + TA, s1, sz);
        }
        for (int u = tid; u < NT * 4; u += 256) {
            int r = u >> 2, c16 = u & 3;
            int gr = n0 + r;
            const bf16* s0 = P.B0 + (size_t)gr * P.ldb + k0 + c16 * 8;
            const bf16* s1 = P.B1 + (size_t)gr * P.ldb + k0 + c16 * 8;
            int sz = (gr < P.N) ? 16 : 0;
            uint32_t d = base + 2 * TA + r * RS + c16 * 16;
            cp16(d, s0, sz);
            cp16(d + TB, s1, sz);
        }
        asm volatile("cp.async.commit_group;" ::: "memory");
    };

    float acc[MT][NTL][4];
    #pragma unroll
    for (int i = 0; i < MT; i++)
        #pragma unroll
        for (int j = 0; j < NTL; j++)
            #pragma unroll
            for (int e = 0; e < 4; e++) acc[i][j][e] = 0.f;

    load_stage(0);

    for (int c = 0; c < nch; c++) {
        if (c + 1 < nch) {
            load_stage(c + 1);
            asm volatile("cp.async.wait_group 1;" ::: "memory");
        } else {
            asm volatile("cp.async.wait_group 0;" ::: "memory");
        }
        __syncthreads();

        uint32_t sA0 = sb + (uint32_t)(c & 1) * STAGE;
        uint32_t sA1 = sA0 + TA;
        uint32_t sB0 = sA0 + 2 * TA;
        uint32_t sB1 = sB0 + TB;

        #pragma unroll
        for (int kk = 0; kk < BK; kk += 16) {
            uint32_t a0f[MT][4], a1f[MT][4];
            #pragma unroll
            for (int mi = 0; mi < MT; mi++) {
                int row = mBase + mi * 16 + (lane & 15);
                int kc = kk + ((lane >> 4) << 3);
                uint32_t off = (uint32_t)(row * RS + kc * 2);
                ldsm_x4(a0f[mi], sA0 + off);
                ldsm_x4(a1f[mi], sA1 + off);
            }
            uint32_t b0f[NTL / 2][4], b1f[NTL / 2][4];
            #pragma unroll
            for (int bi = 0; bi < NTL / 2; bi++) {
                int row = nBase + bi * 16 + (lane & 7) + ((lane >> 4) << 3);
                int kc = kk + (((lane >> 3) & 1) << 3);
                uint32_t off = (uint32_t)(row * RS + kc * 2);
                ldsm_x4(b0f[bi], sB0 + off);
                ldsm_x4(b1f[bi], sB1 + off);
            }
            #pragma unroll
            for (int mi = 0; mi < MT; mi++)
                #pragma unroll
                for (int ni = 0; ni < NTL; ni++) {
                    const uint32_t* bb0 = &b0f[ni >> 1][(ni & 1) * 2];
                    const uint32_t* bb1 = &b1f[ni >> 1][(ni & 1) * 2];
                    mma16816(acc[mi][ni], a0f[mi], bb0);
                    mma16816(acc[mi][ni], a0f[mi], bb1);
                    mma16816(acc[mi][ni], a1f[mi], bb0);
                }
        }
        __syncthreads();
    }

    // ---- epilogue ----
    #pragma unroll
    for (int mi = 0; mi < MT; mi++) {
        #pragma unroll
        for (int e = 0; e < 4; e++) {
            int m = m0 + mBase + mi * 16 + (lane >> 2) + ((e >> 1) << 3);
            if (m >= P.M) continue;
            int row = REMAP ? (m + m / 196 + 1) : m;
            float* crow = P.C + (size_t)row * P.ldc;
            #pragma unroll
            for (int ni = 0; ni < NTL; ni++) {
                int n = n0 + nBase + ni * 8 + (lane & 3) * 2 + (e & 1);
                float v = acc[mi][ni][e];
                if (P.bias) v += __ldg(P.bias + n);
                if (ACT == 1) v = softplus_f(v);
                crow[n] = v;
                if (P.C0 != nullptr && n < P.split_cols) {
                    bf16 h0 = __float2bfloat16_rn(v);
                    P.C0[(size_t)m * P.split_cols + n] = h0;
                    P.C1[(size_t)m * P.split_cols + n] = __float2bfloat16_rn(v - __bfloat162float(h0));
                }
            }
        }
    }
}

// ---------------- dual selective scan (both directions in one launch) ----------------
__global__ void __launch_bounds__(256)
scan2_kernel(const float* __restrict__ uF, const float* __restrict__ dF,
             const float* __restrict__ bcF, float* __restrict__ yF,
             const float* __restrict__ uB, const float* __restrict__ dB,
             const float* __restrict__ bcB, float* __restrict__ yB,
             const float* __restrict__ A_log, const float* __restrict__ D)
{
    const float* u;  const float* dlt; const float* dbc; float* y;
    if (blockIdx.y == 0) { u = uF; dlt = dF; dbc = bcF; y = yF; }
    else                 { u = uB; dlt = dB; dbc = bcB; y = yB; }

    int g = blockIdx.x * 16 + (threadIdx.x >> 4);   // (b*768+ed)
    int n = threadIdx.x & 15;
    int b = g / DIM;
    int ed = g % DIM;

    float Aval = -__expf(A_log[ed * DSTATE + n]);
    float Dv = D[ed];
    float state = 0.f;

    const float* up = u   + (size_t)(b * SEQ) * DIM + ed;
    const float* dp = dlt + (size_t)(b * SEQ) * DIM + ed;
    const float* bc = dbc + (size_t)(b * SEQ) * 64;
    float*       yp = y   + (size_t)(b * SEQ) * DIM + ed;

    for (int l = 0; l < SEQ; l++) {
        float dv = dp[(size_t)l * DIM];
        float uv = up[(size_t)l * DIM];
        float Bv = bc[l * 64 + DTRANK + n];
        float Cv = bc[l * 64 + DTRANK + DSTATE + n];
        float dA = __expf(dv * Aval);
        state = state * dA + dv * Bv * uv;
        float part = state * Cv;
        part += __shfl_down_sync(0xffffffffu, part, 8, 16);
        part += __shfl_down_sync(0xffffffffu, part, 4, 16);
        part += __shfl_down_sync(0xffffffffu, part, 2, 16);
        part += __shfl_down_sync(0xffffffffu, part, 1, 16);
        if (n == 0) yp[(size_t)l * DIM] = part + Dv * uv;
    }
}

// ---------------- classification head ----------------
__global__ void head_kernel(const float* __restrict__ pin, const float* __restrict__ W,
                            const float* __restrict__ bias, float* __restrict__ out) {
    int b = blockIdx.x;
    __shared__ float sh[DIM];
    for (int i = threadIdx.x; i < DIM; i += blockDim.x) sh[i] = pin[b * DIM + i];
    __syncthreads();
    for (int cls = blockIdx.y * blockDim.x + threadIdx.x; cls < NCLS;
         cls += gridDim.y * blockDim.x) {
        float acc = bias[cls];
        for (int k = 0; k < DIM; k++) acc = fmaf(sh[k], W[(size_t)k * NCLS + cls], acc);
        out[b * NCLS + cls] = acc;
    }
}

// ---------------- launch ----------------
extern "C" void kernel_launch(void* const* d_in, const int* in_sizes, int n_in,
                              void* d_out, int out_size)
{
    const float* x        = (const float*)d_in[0];
    const float* patch_W  = (const float*)d_in[1];
    const float* patch_b  = (const float*)d_in[2];
    const float* cls_tok  = (const float*)d_in[3];
    const float* norm_g   = (const float*)d_in[4];
    const float* norm_b   = (const float*)d_in[5];
    const float* proj_W   = (const float*)d_in[6];
    const float* proj_b   = (const float*)d_in[7];
    const float* fconv_W  = (const float*)d_in[8];
    const float* fconv_b  = (const float*)d_in[9];
    const float* bconv_W  = (const float*)d_in[10];
    const float* bconv_b  = (const float*)d_in[11];
    const float* dbc_W    = (const float*)d_in[12];
    const float* dt_W     = (const float*)d_in[13];
    const float* dt_b     = (const float*)d_in[14];
    const float* A_log    = (const float*)d_in[15];
    const float* D_ssm    = (const float*)d_in[16];
    const float* head_g   = (const float*)d_in[17];
    const float* head_b   = (const float*)d_in[18];
    const float* head_W   = (const float*)d_in[19];
    const float* head_bias= (const float*)d_in[20];
    float* out = (float*)d_out;

    float *h, *xz, *uf, *ub, *dbcf, *dbcb, *df, *db_, *y1, *y2, *pool, *pooln;
    cudaGetSymbolAddress((void**)&h,    g_h);
    cudaGetSymbolAddress((void**)&xz,   g_xz);
    cudaGetSymbolAddress((void**)&uf,   g_uf);
    cudaGetSymbolAddress((void**)&ub,   g_ub);
    cudaGetSymbolAddress((void**)&dbcf, g_dbcf);
    cudaGetSymbolAddress((void**)&dbcb, g_dbcb);
    cudaGetSymbolAddress((void**)&df,   g_df);
    cudaGetSymbolAddress((void**)&db_,  g_db);
    cudaGetSymbolAddress((void**)&y1,   g_y1);
    cudaGetSymbolAddress((void**)&y2,   g_y2);
    cudaGetSymbolAddress((void**)&pool, g_pool);
    cudaGetSymbolAddress((void**)&pooln,g_pooln);
    bf16 *xp0,*xp1,*xn0,*xn1,*xz0,*xz1,*uf0,*uf1,*ub0,*ub1,*dtf0,*dtf1,*dtb0,*dtb1;
    cudaGetSymbolAddress((void**)&xp0, g_xp0);  cudaGetSymbolAddress((void**)&xp1, g_xp1);
    cudaGetSymbolAddress((void**)&xn0, g_xn0);  cudaGetSymbolAddress((void**)&xn1, g_xn1);
    cudaGetSymbolAddress((void**)&xz0, g_xz0);  cudaGetSymbolAddress((void**)&xz1, g_xz1);
    cudaGetSymbolAddress((void**)&uf0, g_uf0);  cudaGetSymbolAddress((void**)&uf1, g_uf1);
    cudaGetSymbolAddress((void**)&ub0, g_ub0);  cudaGetSymbolAddress((void**)&ub1, g_ub1);
    cudaGetSymbolAddress((void**)&dtf0,g_dtf0); cudaGetSymbolAddress((void**)&dtf1,g_dtf1);
    cudaGetSymbolAddress((void**)&dtb0,g_dtb0); cudaGetSymbolAddress((void**)&dtb1,g_dtb1);
    bf16 *wp0,*wp1,*wf0,*wf1,*wb0,*wb1,*wd0,*wd1,*wt0,*wt1,*wa0,*wa1;
    cudaGetSymbolAddress((void**)&wp0, g_wproj0);  cudaGetSymbolAddress((void**)&wp1, g_wproj1);
    cudaGetSymbolAddress((void**)&wf0, g_wfconv0); cudaGetSymbolAddress((void**)&wf1, g_wfconv1);
    cudaGetSymbolAddress((void**)&wb0, g_wbconv0); cudaGetSymbolAddress((void**)&wb1, g_wbconv1);
    cudaGetSymbolAddress((void**)&wd0, g_wdbc0);   cudaGetSymbolAddress((void**)&wd1, g_wdbc1);
    cudaGetSymbolAddress((void**)&wt0, g_wdt0);    cudaGetSymbolAddress((void**)&wt1, g_wdt1);
    cudaGetSymbolAddress((void**)&wa0, g_wpat0);   cudaGetSymbolAddress((void**)&wa1, g_wpat1);

    const int SMEM_BIG = 2 * (2 * 128 * 80 + 2 * 128 * 80);  // 81920
    const int SMEM_DBC = 2 * (2 *  64 * 80 + 2 *  64 * 80);  // 40960
    cudaFuncSetAttribute(mma_gemm_kernel<128,128,0,false>, cudaFuncAttributeMaxDynamicSharedMemorySize, SMEM_BIG);
    cudaFuncSetAttribute(mma_gemm_kernel<128,128,0,true >, cudaFuncAttributeMaxDynamicSharedMemorySize, SMEM_BIG);
    cudaFuncSetAttribute(mma_gemm_kernel<128,128,1,false>, cudaFuncAttributeMaxDynamicSharedMemorySize, SMEM_BIG);
    cudaFuncSetAttribute(mma_gemm_kernel<64 ,64 ,0,false>, cudaFuncAttributeMaxDynamicSharedMemorySize, SMEM_DBC);

    const dim3 gBig (DIM / 128, (MTOK + 127) / 128, 1);   // (6, 25, 1)
    const dim3 gBig2(DIM / 128, (MTOK + 127) / 128, 2);   // (6, 25, 2)
    const dim3 gPat (DIM / 128, (TPAT + 127) / 128, 1);
    const dim3 gDbc2(1, (MTOK + 63) / 64, 2);             // (1, 50, 2)

    // ---- weight conversions ----
    {
        int n = DEPTH * DIM * DIM;
        split_direct_kernel<<<(n + 255) / 256, 256>>>(fconv_W, wf0, wf1, n);
        split_direct_kernel<<<(n + 255) / 256, 256>>>(bconv_W, wb0, wb1, n);
        dim3 blk(32, 8);
        split_transpose_kernel<<<dim3(24, 24, DEPTH), blk>>>(proj_W, wp0, wp1, DIM, DIM);
        split_transpose_kernel<<<dim3(2, 24, DEPTH), blk>>>(dbc_W, wd0, wd1, DIM, 64);
        split_transpose_kernel<<<dim3(24, 1, DEPTH), blk>>>(dt_W, wt0, wt1, DTRANK, DIM);
        split_transpose_kernel<<<dim3(24, 24, 1), blk>>>(patch_W, wa0, wa1, DIM, DIM);
    }

    // ---- patch embed ----
    patchify_split_kernel<<<(TPAT * DIM) / 256, 256>>>(x, xp0, xp1);
    cls_init_kernel<<<(BATCH * DIM) / 256, 256>>>(cls_tok, h);
    {
        GemmArgs a{ xp0, xp1, DIM, wa0, wa1, DIM, patch_b, h, DIM,
                    nullptr, nullptr, 0, TPAT, DIM, DIM };
        mma_gemm_kernel<128,128,0,true><<<gPat, 256, SMEM_BIG>>>(a, a);
    }
    ln_kernel<true><<<MTOK, 256>>>(h, nullptr, xn0, xn1, norm_g, norm_b);

    for (int i = 0; i < DEPTH; i++) {
        const size_t wo  = (size_t)i * DIM * DIM;
        const size_t wod = (size_t)i * 64 * DIM;
        const size_t wot = (size_t)i * DIM * DTRANK;

        // xz = xn @ proj_W + proj_b   (+ splits)
        {
            GemmArgs a{ xn0, xn1, DIM, wp0 + wo, wp1 + wo, DIM, proj_b + i*DIM,
                        xz, DIM, xz0, xz1, DIM, MTOK, DIM, DIM };
            mma_gemm_kernel<128,128,0,false><<<gBig, 256, SMEM_BIG>>>(a, a);
        }
        // u = softplus(xz @ convW^T + convb)  (f and b in one launch, + splits)
        {
            GemmArgs a{ xz0, xz1, DIM, wf0 + wo, wf1 + wo, DIM, fconv_b + i*DIM,
                        uf, DIM, uf0, uf1, DIM, MTOK, DIM, DIM };
            GemmArgs b{ xz0, xz1, DIM, wb0 + wo, wb1 + wo, DIM, bconv_b + i*DIM,
                        ub, DIM, ub0, ub1, DIM, MTOK, DIM, DIM };
            mma_gemm_kernel<128,128,1,false><<<gBig2, 256, SMEM_BIG>>>(a, b);
        }
        // dbc = u @ dbc_W  (both directions, BM=64; split first 32 cols = dt input)
        {
            GemmArgs a{ uf0, uf1, DIM, wd0 + wod, wd1 + wod, DIM, nullptr,
                        dbcf, 64, dtf0, dtf1, DTRANK, MTOK, 64, DIM };
            GemmArgs b{ ub0, ub1, DIM, wd0 + wod, wd1 + wod, DIM, nullptr,
                        dbcb, 64, dtb0, dtb1, DTRANK, MTOK, 64, DIM };
            mma_gemm_kernel<64,64,0,false><<<gDbc2, 256, SMEM_DBC>>>(a, b);
        }
        // delta = softplus(dt @ dt_W + dt_b)  (both directions)
        {
            GemmArgs a{ dtf0, dtf1, DTRANK, wt0 + wot, wt1 + wot, DTRANK, dt_b + i*DIM,
                        df, DIM, nullptr, nullptr, 0, MTOK, DIM, DTRANK };
            GemmArgs b{ dtb0, dtb1, DTRANK, wt0 + wot, wt1 + wot, DTRANK, dt_b + i*DIM,
                        db_, DIM, nullptr, nullptr, 0, MTOK, DIM, DTRANK };
            mma_gemm_kernel<128,128,1,false><<<gBig2, 256, SMEM_BIG>>>(a, b);
        }
        // both scans in one launch
        scan2_kernel<<<dim3((BATCH * DIM) / 16, 2), 256>>>(
            uf, df, dbcf, y1, ub, db_, dbcb, y2,
            A_log + (size_t)i*DIM*DSTATE, D_ssm + i*DIM);
        // combine + next-layer LN (or final pool)
        if (i < DEPTH - 1) {
            combine_ln_kernel<<<MTOK, 256>>>(h, xz, y1, y2,
                norm_g + (i+1)*DIM, norm_b + (i+1)*DIM, xn0, xn1);
        } else {
            combine_pool_kernel<<<dim3(BATCH, 3), 256>>>(h, xz, y1, y2, pool);
        }
    }

    ln_kernel<false><<<BATCH, 256>>>(pool, pooln, nullptr, nullptr, head_g, head_b);
    head_kernel<<<dim3(BATCH, 4), 256>>>(pooln, head_W, head_bias, out);
}

// round 6
// speedup vs baseline: 2.0897x; 1.0350x over previous
#include <cuda_runtime.h>
#include <cuda_bf16.h>
#include <math.h>
#include <stdint.h>

typedef __nv_bfloat16 bf16;

// ---------------- problem constants ----------------
#define DIM     768
#define BATCH   16
#define SEQ     197
#define MTOK    (BATCH*SEQ)     // 3152
#define NPATCH  196
#define TPAT    (BATCH*NPATCH)  // 3136
#define DSTATE  16
#define DTRANK  32
#define NCLS    1000
#define DEPTH   12
#define M2      (2*MTOK)        // 6304 (stacked f/b)

// ---------------- static device scratch (allocation-free) ----------------
__device__ float g_h    [MTOK*DIM];
__device__ float g_xz   [MTOK*DIM];
__device__ float g_u    [M2*DIM];      // fwd rows 0..3151, bwd rows 3152..6303
__device__ float g_dbc  [M2*64];
__device__ float g_delta[M2*DIM];
__device__ float g_y    [M2*DIM];
__device__ float g_pool [BATCH*DIM];
__device__ float g_pooln[BATCH*DIM];
// bf16 split activations
__device__ bf16 g_xp0 [TPAT*DIM], g_xp1 [TPAT*DIM];
__device__ bf16 g_xn0 [MTOK*DIM], g_xn1 [MTOK*DIM];
__device__ bf16 g_xz0 [MTOK*DIM], g_xz1 [MTOK*DIM];
__device__ bf16 g_u0  [M2*DIM],   g_u1  [M2*DIM];
__device__ bf16 g_dt0 [M2*DTRANK],g_dt1 [M2*DTRANK];
// bf16 split weights ((N,K) row-major = K-major "col" operand)
__device__ bf16 g_wproj0 [DEPTH*DIM*DIM],  g_wproj1 [DEPTH*DIM*DIM];
__device__ bf16 g_wconv0 [DEPTH*1536*DIM], g_wconv1 [DEPTH*1536*DIM];  // [Wf;Wb] stacked in N
__device__ bf16 g_wdbc0  [DEPTH*64*DIM],   g_wdbc1  [DEPTH*64*DIM];
__device__ bf16 g_wdt0   [DEPTH*DIM*DTRANK], g_wdt1 [DEPTH*DIM*DTRANK];
__device__ bf16 g_wpat0  [DIM*DIM],        g_wpat1  [DIM*DIM];
__device__ float g_convb [DEPTH*1536];     // stacked conv bias

// ---------------- helpers ----------------
__device__ __forceinline__ float softplus_f(float x) {
    if (x > 20.f) return x;
    return log1pf(__expf(x));
}
__device__ __forceinline__ uint32_t smem_u32(const void* p) {
    uint32_t a;
    asm("{ .reg .u64 t; cvta.to.shared.u64 t, %1; cvt.u32.u64 %0, t; }" : "=r"(a) : "l"(p));
    return a;
}
__device__ __forceinline__ void cp16(uint32_t dst, const void* src, int sz) {
    asm volatile("cp.async.ca.shared.global [%0], [%1], 16, %2;"
                 :: "r"(dst), "l"(src), "r"(sz));
}
__device__ __forceinline__ void ldsm_x4(uint32_t* r, uint32_t addr) {
    asm volatile("ldmatrix.sync.aligned.m8n8.x4.shared.b16 {%0,%1,%2,%3}, [%4];"
                 : "=r"(r[0]), "=r"(r[1]), "=r"(r[2]), "=r"(r[3]) : "r"(addr));
}
__device__ __forceinline__ void mma16816(float* d, const uint32_t* a, const uint32_t* b) {
    asm volatile("mma.sync.aligned.m16n8k16.row.col.f32.bf16.bf16.f32 "
                 "{%0,%1,%2,%3}, {%4,%5,%6,%7}, {%8,%9}, {%0,%1,%2,%3};"
                 : "+f"(d[0]), "+f"(d[1]), "+f"(d[2]), "+f"(d[3])
                 : "r"(a[0]), "r"(a[1]), "r"(a[2]), "r"(a[3]), "r"(b[0]), "r"(b[1]));
}

// ---------------- weight preparation ----------------
// stack fconv/bconv (DEPTH,DIM,DIM) row-major into (DEPTH,1536,DIM) bf16 splits
__global__ void conv_stack_split_kernel(const float* __restrict__ f, const float* __restrict__ b,
                                        bf16* __restrict__ o0, bf16* __restrict__ o1) {
    int idx = blockIdx.x * blockDim.x + threadIdx.x;   // < DEPTH*DIM*DIM
    if (idx >= DEPTH * DIM * DIM) return;
    int i = idx / (DIM * DIM);
    int r = (idx / DIM) % DIM;
    int d = idx % DIM;
    size_t df_ = ((size_t)i * 1536 + r) * DIM + d;
    size_t db_ = ((size_t)i * 1536 + 768 + r) * DIM + d;
    float vf = f[idx], vb = b[idx];
    bf16 h0;
    h0 = __float2bfloat16_rn(vf); o0[df_] = h0; o1[df_] = __float2bfloat16_rn(vf - __bfloat162float(h0));
    h0 = __float2bfloat16_rn(vb); o0[db_] = h0; o1[db_] = __float2bfloat16_rn(vb - __bfloat162float(h0));
}
__global__ void bias_stack_kernel(const float* __restrict__ f, const float* __restrict__ b,
                                  float* __restrict__ o) {
    int idx = blockIdx.x * blockDim.x + threadIdx.x;   // < DEPTH*DIM
    if (idx >= DEPTH * DIM) return;
    int i = idx / DIM, d = idx % DIM;
    o[i * 1536 + d] = f[idx];
    o[i * 1536 + 768 + d] = b[idx];
}
// split + transpose: in[z] (R,C) -> out[z] (C,R)
__global__ void split_transpose_kernel(const float* __restrict__ in,
                                       bf16* __restrict__ o0, bf16* __restrict__ o1,
                                       int R, int C) {
    __shared__ float t[32][33];
    size_t off = (size_t)blockIdx.z * R * C;
    int r0 = blockIdx.y * 32, c0 = blockIdx.x * 32;
    int tx = threadIdx.x, ty = threadIdx.y;
    #pragma unroll
    for (int i = 0; i < 32; i += 8) {
        int rr = r0 + ty + i, cc = c0 + tx;
        t[ty + i][tx] = (rr < R && cc < C) ? in[off + (size_t)rr * C + cc] : 0.f;
    }
    __syncthreads();
    #pragma unroll
    for (int i = 0; i < 32; i += 8) {
        int oc = c0 + ty + i, orr = r0 + tx;
        if (oc < C && orr < R) {
            float v = t[tx][ty + i];
            bf16 h0 = __float2bfloat16_rn(v);
            o0[off + (size_t)oc * R + orr] = h0;
            o1[off + (size_t)oc * R + orr] = __float2bfloat16_rn(v - __bfloat162float(h0));
        }
    }
}

// ---------------- patchify -> bf16 splits ----------------
__global__ void patchify_split_kernel(const float* __restrict__ x,
                                      bf16* __restrict__ o0, bf16* __restrict__ o1) {
    int idx = blockIdx.x * blockDim.x + threadIdx.x;   // < TPAT*DIM
    int t = idx / DIM, f = idx % DIM;
    int b = t / NPATCH, hw = t % NPATCH;
    int hh = hw / 14, ww = hw % 14;
    int c = f % 3, pp = f / 3;
    int p1 = pp / 16, p2 = pp % 16;
    float v = x[(((size_t)(b * 3 + c) * 224) + hh * 16 + p1) * 224 + ww * 16 + p2];
    bf16 h0 = __float2bfloat16_rn(v);
    o0[idx] = h0;
    o1[idx] = __float2bfloat16_rn(v - __bfloat162float(h0));
}

__global__ void cls_init_kernel(const float* __restrict__ cls, float* __restrict__ h) {
    int idx = blockIdx.x * blockDim.x + threadIdx.x;   // < BATCH*DIM
    int b = idx / DIM, d = idx % DIM;
    h[(size_t)b * SEQ * DIM + d] = cls[d];
}

// ---------------- layernorm ----------------
template<bool SPLIT>
__global__ void ln_kernel(const float* __restrict__ in, float* __restrict__ outf,
                          bf16* __restrict__ o0, bf16* __restrict__ o1,
                          const float* __restrict__ g, const float* __restrict__ bv) {
    int row = blockIdx.x;
    const float* xr = in + (size_t)row * DIM;
    int tid = threadIdx.x;
    float v0 = xr[tid], v1 = xr[tid + 256], v2 = xr[tid + 512];
    __shared__ float red[256];
    red[tid] = v0 + v1 + v2;
    __syncthreads();
    #pragma unroll
    for (int o = 128; o > 0; o >>= 1) { if (tid < o) red[tid] += red[tid + o]; __syncthreads(); }
    float mean = red[0] * (1.f / 768.f);
    __syncthreads();
    float d0 = v0 - mean, d1 = v1 - mean, d2 = v2 - mean;
    red[tid] = d0 * d0 + d1 * d1 + d2 * d2;
    __syncthreads();
    #pragma unroll
    for (int o = 128; o > 0; o >>= 1) { if (tid < o) red[tid] += red[tid + o]; __syncthreads(); }
    float rstd = rsqrtf(red[0] * (1.f / 768.f) + 1e-5f);
    float r0 = d0 * rstd * g[tid]       + bv[tid];
    float r1 = d1 * rstd * g[tid + 256] + bv[tid + 256];
    float r2 = d2 * rstd * g[tid + 512] + bv[tid + 512];
    if (SPLIT) {
        size_t base = (size_t)row * DIM;
        bf16 h0;
        h0 = __float2bfloat16_rn(r0); o0[base + tid]       = h0; o1[base + tid]       = __float2bfloat16_rn(r0 - __bfloat162float(h0));
        h0 = __float2bfloat16_rn(r1); o0[base + tid + 256] = h0; o1[base + tid + 256] = __float2bfloat16_rn(r1 - __bfloat162float(h0));
        h0 = __float2bfloat16_rn(r2); o0[base + tid + 512] = h0; o1[base + tid + 512] = __float2bfloat16_rn(r2 - __bfloat162float(h0));
    } else {
        float* orow = outf + (size_t)row * DIM;
        orow[tid] = r0; orow[tid + 256] = r1; orow[tid + 512] = r2;
    }
}

// ---------------- fused combine + layernorm + split ----------------
__global__ void combine_ln_kernel(float* __restrict__ h, const float* __restrict__ xz,
                                  const float* __restrict__ y1, const float* __restrict__ y2,
                                  const float* __restrict__ g, const float* __restrict__ bv,
                                  bf16* __restrict__ o0, bf16* __restrict__ o1) {
    int row = blockIdx.x;
    int tid = threadIdx.x;
    size_t base = (size_t)row * DIM;
    float v[3];
    #pragma unroll
    for (int e = 0; e < 3; e++) {
        size_t idx = base + tid + e * 256;
        float z = xz[idx];
        z = z / (1.f + __expf(-z));
        float val = h[idx] + (y1[idx] + y2[idx]) * z;
        h[idx] = val;
        v[e] = val;
    }
    __shared__ float red[256];
    red[tid] = v[0] + v[1] + v[2];
    __syncthreads();
    #pragma unroll
    for (int o = 128; o > 0; o >>= 1) { if (tid < o) red[tid] += red[tid + o]; __syncthreads(); }
    float mean = red[0] * (1.f / 768.f);
    __syncthreads();
    float d0 = v[0] - mean, d1 = v[1] - mean, d2 = v[2] - mean;
    red[tid] = d0 * d0 + d1 * d1 + d2 * d2;
    __syncthreads();
    #pragma unroll
    for (int o = 128; o > 0; o >>= 1) { if (tid < o) red[tid] += red[tid + o]; __syncthreads(); }
    float rstd = rsqrtf(red[0] * (1.f / 768.f) + 1e-5f);
    float r0 = d0 * rstd * g[tid]       + bv[tid];
    float r1 = d1 * rstd * g[tid + 256] + bv[tid + 256];
    float r2 = d2 * rstd * g[tid + 512] + bv[tid + 512];
    bf16 h0;
    h0 = __float2bfloat16_rn(r0); o0[base + tid]       = h0; o1[base + tid]       = __float2bfloat16_rn(r0 - __bfloat162float(h0));
    h0 = __float2bfloat16_rn(r1); o0[base + tid + 256] = h0; o1[base + tid + 256] = __float2bfloat16_rn(r1 - __bfloat162float(h0));
    h0 = __float2bfloat16_rn(r2); o0[base + tid + 512] = h0; o1[base + tid + 512] = __float2bfloat16_rn(r2 - __bfloat162float(h0));
}

// ---------------- fused final combine + mean pool ----------------
__global__ void combine_pool_kernel(const float* __restrict__ h, const float* __restrict__ xz,
                                    const float* __restrict__ y1, const float* __restrict__ y2,
                                    float* __restrict__ pooled) {
    int b = blockIdx.x;
    int d = blockIdx.y * blockDim.x + threadIdx.x;
    float s = 0.f;
    size_t base = (size_t)(b * SEQ) * DIM + d;
    for (int l = 0; l < SEQ; l++) {
        size_t idx = base + (size_t)l * DIM;
        float z = xz[idx];
        z = z / (1.f + __expf(-z));
        s += h[idx] + (y1[idx] + y2[idx]) * z;
    }
    pooled[b * DIM + d] = s * (1.f / (float)SEQ);
}

// ---------------- warp-MMA GEMM (mma.sync bf16, 3-term compensated) ----------------
// MODE: 0 = plain, 1 = patch row remap (m + m/196 + 1), 2 = dual-N (cols>=768 -> rows+MTOK)
struct GemmArgs {
    const bf16 *A0, *A1; int lda;
    const bf16 *B0, *B1; int ldb;
    const float* bias;
    float* C; int ldc;
    bf16 *C0, *C1; int split_cols;
    int M, N, K;
};

template<int BM, int NT, int ACT, int MODE>
__global__ void __launch_bounds__(256, 2)
mma_gemm_kernel(const GemmArgs P)
{
    constexpr int BK = 32;
    constexpr int WGM = (NT == 128) ? 2 : 4;
    constexpr int WGN = 8 / WGM;
    constexpr int WM = BM / WGM;
    constexpr int WN = NT / WGN;
    constexpr int MT = WM / 16;
    constexpr int NTL = WN / 8;
    constexpr int RS = 80;
    constexpr int TA = BM * RS;
    constexpr int TB = NT * RS;
    constexpr int STAGE = 2 * TA + 2 * TB;

    extern __shared__ char smem[];
    uint32_t sb = smem_u32(smem);
    int tid = threadIdx.x, wid = tid >> 5, lane = tid & 31;
    int n0 = blockIdx.x * NT, m0 = blockIdx.y * BM;
    int wm = wid & (WGM - 1), wn = wid / WGM;
    int mBase = wm * WM, nBase = wn * WN;

    const int nch = P.K >> 5;

    auto load_stage = [&](int c) {
        uint32_t base = sb + (uint32_t)(c & 1) * STAGE;
        int k0 = c << 5;
        for (int u = tid; u < BM * 4; u += 256) {
            int r = u >> 2, c16 = u & 3;
            int gr = m0 + r;
            const bf16* s0 = P.A0 + (size_t)gr * P.lda + k0 + c16 * 8;
            const bf16* s1 = P.A1 + (size_t)gr * P.lda + k0 + c16 * 8;
            int sz = (gr < P.M) ? 16 : 0;
            uint32_t d = base + r * RS + c16 * 16;
            cp16(d, s0, sz);
            cp16(d + TA, s1, sz);
        }
        for (int u = tid; u < NT * 4; u += 256) {
            int r = u >> 2, c16 = u & 3;
            int gr = n0 + r;
            const bf16* s0 = P.B0 + (size_t)gr * P.ldb + k0 + c16 * 8;
            const bf16* s1 = P.B1 + (size_t)gr * P.ldb + k0 + c16 * 8;
            int sz = (gr < P.N) ? 16 : 0;
            uint32_t d = base + 2 * TA + r * RS + c16 * 16;
            cp16(d, s0, sz);
            cp16(d + TB, s1, sz);
        }
        asm volatile("cp.async.commit_group;" ::: "memory");
    };

    float acc[MT][NTL][4];
    #pragma unroll
    for (int i = 0; i < MT; i++)
        #pragma unroll
        for (int j = 0; j < NTL; j++)
            #pragma unroll
            for (int e = 0; e < 4; e++) acc[i][j][e] = 0.f;

    load_stage(0);

    for (int c = 0; c < nch; c++) {
        if (c + 1 < nch) {
            load_stage(c + 1);
            asm volatile("cp.async.wait_group 1;" ::: "memory");
        } else {
            asm volatile("cp.async.wait_group 0;" ::: "memory");
        }
        __syncthreads();

        uint32_t sA0 = sb + (uint32_t)(c & 1) * STAGE;
        uint32_t sA1 = sA0 + TA;
        uint32_t sB0 = sA0 + 2 * TA;
        uint32_t sB1 = sB0 + TB;

        #pragma unroll
        for (int kk = 0; kk < BK; kk += 16) {
            // B fragments first (lower register pressure)
            uint32_t b0f[NTL / 2][4], b1f[NTL / 2][4];
            #pragma unroll
            for (int bi = 0; bi < NTL / 2; bi++) {
                int row = nBase + bi * 16 + (lane & 7) + ((lane >> 4) << 3);
                int kc = kk + (((lane >> 3) & 1) << 3);
                uint32_t off = (uint32_t)(row * RS + kc * 2);
                ldsm_x4(b0f[bi], sB0 + off);
                ldsm_x4(b1f[bi], sB1 + off);
            }
            #pragma unroll
            for (int mi = 0; mi < MT; mi++) {
                uint32_t a0f[4], a1f[4];
                {
                    int row = mBase + mi * 16 + (lane & 15);
                    int kc = kk + ((lane >> 4) << 3);
                    uint32_t off = (uint32_t)(row * RS + kc * 2);
                    ldsm_x4(a0f, sA0 + off);
                    ldsm_x4(a1f, sA1 + off);
                }
                #pragma unroll
                for (int ni = 0; ni < NTL; ni++) {
                    const uint32_t* bb0 = &b0f[ni >> 1][(ni & 1) * 2];
                    const uint32_t* bb1 = &b1f[ni >> 1][(ni & 1) * 2];
                    mma16816(acc[mi][ni], a0f, bb0);
                    mma16816(acc[mi][ni], a0f, bb1);
                    mma16816(acc[mi][ni], a1f, bb0);
                }
            }
        }
        __syncthreads();
    }

    // ---- epilogue ----
    #pragma unroll
    for (int mi = 0; mi < MT; mi++) {
        #pragma unroll
        for (int e = 0; e < 4; e++) {
            int m = m0 + mBase + mi * 16 + (lane >> 2) + ((e >> 1) << 3);
            if (m >= P.M) continue;
            #pragma unroll
            for (int ni = 0; ni < NTL; ni++) {
                int n = n0 + nBase + ni * 8 + (lane & 3) * 2 + (e & 1);
                float v = acc[mi][ni][e];
                if (P.bias) v += __ldg(P.bias + n);
                if (ACT == 1) v = softplus_f(v);
                int mm = m, nn = n;
                if (MODE == 2 && n >= DIM) { mm = m + MTOK; nn = n - DIM; }
                int row = (MODE == 1) ? (m + m / 196 + 1) : mm;
                P.C[(size_t)row * P.ldc + nn] = v;
                if (P.C0 != nullptr && nn < P.split_cols) {
                    bf16 h0 = __float2bfloat16_rn(v);
                    P.C0[(size_t)mm * P.split_cols + nn] = h0;
                    P.C1[(size_t)mm * P.split_cols + nn] = __float2bfloat16_rn(v - __bfloat162float(h0));
                }
            }
        }
    }
}

// ---------------- dual selective scan (both directions via blockIdx.y) ----------------
__global__ void __launch_bounds__(256)
scan2_kernel(const float* __restrict__ u, const float* __restrict__ dlt,
             const float* __restrict__ dbc, float* __restrict__ y,
             const float* __restrict__ A_log, const float* __restrict__ D)
{
    int dir = blockIdx.y;
    u   += (size_t)dir * MTOK * DIM;
    dlt += (size_t)dir * MTOK * DIM;
    dbc += (size_t)dir * MTOK * 64;
    y   += (size_t)dir * MTOK * DIM;

    int g = blockIdx.x * 16 + (threadIdx.x >> 4);   // (b*768+ed)
    int n = threadIdx.x & 15;
    int b = g / DIM;
    int ed = g % DIM;

    float Aval = -__expf(A_log[ed * DSTATE + n]);
    float Dv = D[ed];
    float state = 0.f;

    const float* up = u   + (size_t)(b * SEQ) * DIM + ed;
    const float* dp = dlt + (size_t)(b * SEQ) * DIM + ed;
    const float* bc = dbc + (size_t)(b * SEQ) * 64;
    float*       yp = y   + (size_t)(b * SEQ) * DIM + ed;

    for (int l = 0; l < SEQ; l++) {
        float dv = dp[(size_t)l * DIM];
        float uv = up[(size_t)l * DIM];
        float Bv = bc[l * 64 + DTRANK + n];
        float Cv = bc[l * 64 + DTRANK + DSTATE + n];
        float dA = __expf(dv * Aval);
        state = state * dA + dv * Bv * uv;
        float part = state * Cv;
        part += __shfl_down_sync(0xffffffffu, part, 8, 16);
        part += __shfl_down_sync(0xffffffffu, part, 4, 16);
        part += __shfl_down_sync(0xffffffffu, part, 2, 16);
        part += __shfl_down_sync(0xffffffffu, part, 1, 16);
        if (n == 0) yp[(size_t)l * DIM] = part + Dv * uv;
    }
}

// ---------------- classification head ----------------
__global__ void head_kernel(const float* __restrict__ pin, const float* __restrict__ W,
                            const float* __restrict__ bias, float* __restrict__ out) {
    int b = blockIdx.x;
    __shared__ float sh[DIM];
    for (int i = threadIdx.x; i < DIM; i += blockDim.x) sh[i] = pin[b * DIM + i];
    __syncthreads();
    for (int cls = blockIdx.y * blockDim.x + threadIdx.x; cls < NCLS;
         cls += gridDim.y * blockDim.x) {
        float acc = bias[cls];
        for (int k = 0; k < DIM; k++) acc = fmaf(sh[k], W[(size_t)k * NCLS + cls], acc);
        out[b * NCLS + cls] = acc;
    }
}

// ---------------- launch ----------------
extern "C" void kernel_launch(void* const* d_in, const int* in_sizes, int n_in,
                              void* d_out, int out_size)
{
    const float* x        = (const float*)d_in[0];
    const float* patch_W  = (const float*)d_in[1];
    const float* patch_b  = (const float*)d_in[2];
    const float* cls_tok  = (const float*)d_in[3];
    const float* norm_g   = (const float*)d_in[4];
    const float* norm_b   = (const float*)d_in[5];
    const float* proj_W   = (const float*)d_in[6];
    const float* proj_b   = (const float*)d_in[7];
    const float* fconv_W  = (const float*)d_in[8];
    const float* fconv_b  = (const float*)d_in[9];
    const float* bconv_W  = (const float*)d_in[10];
    const float* bconv_b  = (const float*)d_in[11];
    const float* dbc_W    = (const float*)d_in[12];
    const float* dt_W     = (const float*)d_in[13];
    const float* dt_b     = (const float*)d_in[14];
    const float* A_log    = (const float*)d_in[15];
    const float* D_ssm    = (const float*)d_in[16];
    const float* head_g   = (const float*)d_in[17];
    const float* head_b   = (const float*)d_in[18];
    const float* head_W   = (const float*)d_in[19];
    const float* head_bias= (const float*)d_in[20];
    float* out = (float*)d_out;

    float *h, *xz, *u, *dbc, *delta, *y, *pool, *pooln, *convb;
    cudaGetSymbolAddress((void**)&h,    g_h);
    cudaGetSymbolAddress((void**)&xz,   g_xz);
    cudaGetSymbolAddress((void**)&u,    g_u);
    cudaGetSymbolAddress((void**)&dbc,  g_dbc);
    cudaGetSymbolAddress((void**)&delta,g_delta);
    cudaGetSymbolAddress((void**)&y,    g_y);
    cudaGetSymbolAddress((void**)&pool, g_pool);
    cudaGetSymbolAddress((void**)&pooln,g_pooln);
    cudaGetSymbolAddress((void**)&convb,g_convb);
    bf16 *xp0,*xp1,*xn0,*xn1,*xz0,*xz1,*u0,*u1,*dt0,*dt1;
    cudaGetSymbolAddress((void**)&xp0, g_xp0);  cudaGetSymbolAddress((void**)&xp1, g_xp1);
    cudaGetSymbolAddress((void**)&xn0, g_xn0);  cudaGetSymbolAddress((void**)&xn1, g_xn1);
    cudaGetSymbolAddress((void**)&xz0, g_xz0);  cudaGetSymbolAddress((void**)&xz1, g_xz1);
    cudaGetSymbolAddress((void**)&u0,  g_u0);   cudaGetSymbolAddress((void**)&u1,  g_u1);
    cudaGetSymbolAddress((void**)&dt0, g_dt0);  cudaGetSymbolAddress((void**)&dt1, g_dt1);
    bf16 *wp0,*wp1,*wc0,*wc1,*wd0,*wd1,*wt0,*wt1,*wa0,*wa1;
    cudaGetSymbolAddress((void**)&wp0, g_wproj0);  cudaGetSymbolAddress((void**)&wp1, g_wproj1);
    cudaGetSymbolAddress((void**)&wc0, g_wconv0);  cudaGetSymbolAddress((void**)&wc1, g_wconv1);
    cudaGetSymbolAddress((void**)&wd0, g_wdbc0);   cudaGetSymbolAddress((void**)&wd1, g_wdbc1);
    cudaGetSymbolAddress((void**)&wt0, g_wdt0);    cudaGetSymbolAddress((void**)&wt1, g_wdt1);
    cudaGetSymbolAddress((void**)&wa0, g_wpat0);   cudaGetSymbolAddress((void**)&wa1, g_wpat1);

    const int SMEM_BIG = 2 * (2 * 128 * 80 + 2 * 128 * 80);  // 81920
    const int SMEM_DBC = 2 * (2 *  64 * 80 + 2 *  64 * 80);  // 40960
    cudaFuncSetAttribute(mma_gemm_kernel<128,128,0,0>, cudaFuncAttributeMaxDynamicSharedMemorySize, SMEM_BIG);
    cudaFuncSetAttribute(mma_gemm_kernel<128,128,0,1>, cudaFuncAttributeMaxDynamicSharedMemorySize, SMEM_BIG);
    cudaFuncSetAttribute(mma_gemm_kernel<128,128,1,2>, cudaFuncAttributeMaxDynamicSharedMemorySize, SMEM_BIG);
    cudaFuncSetAttribute(mma_gemm_kernel<128,128,1,0>, cudaFuncAttributeMaxDynamicSharedMemorySize, SMEM_BIG);
    cudaFuncSetAttribute(mma_gemm_kernel<64 ,64 ,0,0>, cudaFuncAttributeMaxDynamicSharedMemorySize, SMEM_DBC);

    // ---- weight preparation ----
    {
        int n = DEPTH * DIM * DIM;
        conv_stack_split_kernel<<<(n + 255) / 256, 256>>>(fconv_W, bconv_W, wc0, wc1);
        bias_stack_kernel<<<(DEPTH * DIM + 255) / 256, 256>>>(fconv_b, bconv_b, convb);
        dim3 blk(32, 8);
        split_transpose_kernel<<<dim3(24, 24, DEPTH), blk>>>(proj_W, wp0, wp1, DIM, DIM);
        split_transpose_kernel<<<dim3(2, 24, DEPTH), blk>>>(dbc_W, wd0, wd1, DIM, 64);
        split_transpose_kernel<<<dim3(24, 1, DEPTH), blk>>>(dt_W, wt0, wt1, DTRANK, DIM);
        split_transpose_kernel<<<dim3(24, 24, 1), blk>>>(patch_W, wa0, wa1, DIM, DIM);
    }

    // ---- patch embed ----
    patchify_split_kernel<<<(TPAT * DIM) / 256, 256>>>(x, xp0, xp1);
    cls_init_kernel<<<(BATCH * DIM) / 256, 256>>>(cls_tok, h);
    {
        GemmArgs a{ xp0, xp1, DIM, wa0, wa1, DIM, patch_b, h, DIM,
                    nullptr, nullptr, 0, TPAT, DIM, DIM };
        mma_gemm_kernel<128,128,0,1><<<dim3(6, 25), 256, SMEM_BIG>>>(a);
    }
    ln_kernel<true><<<MTOK, 256>>>(h, nullptr, xn0, xn1, norm_g, norm_b);

    for (int i = 0; i < DEPTH; i++) {
        const size_t wo  = (size_t)i * DIM * DIM;
        const size_t woc = (size_t)i * 1536 * DIM;
        const size_t wod = (size_t)i * 64 * DIM;
        const size_t wot = (size_t)i * DIM * DTRANK;

        // xz = xn @ proj_W + proj_b   (+ splits)   150 tiles
        {
            GemmArgs a{ xn0, xn1, DIM, wp0 + wo, wp1 + wo, DIM, proj_b + i*DIM,
                        xz, DIM, xz0, xz1, DIM, MTOK, DIM, DIM };
            mma_gemm_kernel<128,128,0,0><<<dim3(6, 25), 256, SMEM_BIG>>>(a);
        }
        // u(f&b) = softplus(xz @ [Wf;Wb]^T + [bf;bb])   N=1536 dual epilogue, 300 tiles
        {
            GemmArgs a{ xz0, xz1, DIM, wc0 + woc, wc1 + woc, DIM, convb + i*1536,
                        u, DIM, u0, u1, DIM, MTOK, 1536, DIM };
            mma_gemm_kernel<128,128,1,2><<<dim3(12, 25), 256, SMEM_BIG>>>(a);
        }
        // dbc = u @ dbc_W  (M=6304 stacked, N=64; split first 32 cols = dt input)
        {
            GemmArgs a{ u0, u1, DIM, wd0 + wod, wd1 + wod, DIM, nullptr,
                        dbc, 64, dt0, dt1, DTRANK, M2, 64, DIM };
            mma_gemm_kernel<64,64,0,0><<<dim3(1, (M2 + 63) / 64), 256, SMEM_DBC>>>(a);
        }
        // delta = softplus(dt @ dt_W + dt_b)  (M=6304 stacked, K=32)
        {
            GemmArgs a{ dt0, dt1, DTRANK, wt0 + wot, wt1 + wot, DTRANK, dt_b + i*DIM,
                        delta, DIM, nullptr, nullptr, 0, M2, DIM, DTRANK };
            mma_gemm_kernel<128,128,1,0><<<dim3(6, (M2 + 127) / 128), 256, SMEM_BIG>>>(a);
        }
        // both scans
        scan2_kernel<<<dim3((BATCH * DIM) / 16, 2), 256>>>(
            u, delta, dbc, y, A_log + (size_t)i*DIM*DSTATE, D_ssm + i*DIM);
        // combine + next-layer LN (or final pool)
        if (i < DEPTH - 1) {
            combine_ln_kernel<<<MTOK, 256>>>(h, xz, y, y + (size_t)MTOK*DIM,
                norm_g + (i+1)*DIM, norm_b + (i+1)*DIM, xn0, xn1);
        } else {
            combine_pool_kernel<<<dim3(BATCH, 3), 256>>>(h, xz, y, y + (size_t)MTOK*DIM, pool);
        }
    }

    ln_kernel<false><<<BATCH, 256>>>(pool, pooln, nullptr, nullptr, head_g, head_b);
    head_kernel<<<dim3(BATCH, 4), 256>>>(pooln, head_W, head_bias, out);
}